// round 5
// baseline (speedup 1.0000x reference)
#include <cuda_runtime.h>

#define EMBED      128
#define HID        64
#define MAX_NODES  50000
#define EPS_F      1e-10f

typedef unsigned long long ull_t;

// Scratch: PQ[n][0:64] = node_embed[n] @ W1[0:128], PQ[n][64:128] = node_embed[n] @ W1[128:256]
__device__ float g_PQ[(size_t)MAX_NODES * 128];
// 1 if edge_index buffer is int64 (little-endian), 0 if int32.
__device__ int g_idx_is64;

// ---------------------------------------------------------------------------
// Kernel 0: detect edge_index dtype (parallel: 32 independent loads + ballot).
// If buffer is int64 with indices < 2^31, every odd 32-bit word is 0.
// 32 random int32 indices in [0, 50000) being all zero is impossible.
// ---------------------------------------------------------------------------
__global__ void detect_idx_dtype_kernel(const int* __restrict__ eidx32, int num_edges)
{
    int lane = threadIdx.x;
    int i = lane < num_edges ? lane : 0;
    int nz = (eidx32[2 * i + 1] != 0) ? 1 : 0;
    unsigned mask = __ballot_sync(0xffffffffu, nz);
    if (lane == 0) g_idx_is64 = (mask == 0u) ? 1 : 0;
}

// packed f32x2 fused multiply-add (SASS FFMA2; 2x fp32 throughput)
__device__ __forceinline__ ull_t ffma2(ull_t a, ull_t b, ull_t c)
{
    ull_t d;
    asm("fma.rn.f32x2 %0, %1, %2, %3;" : "=l"(d) : "l"(a), "l"(b), "l"(c));
    return d;
}

// ---------------------------------------------------------------------------
// Kernel 1: PQ = node_embed(50000x128) @ W_eff(128x128), packed f32x2 FFMA.
// W_eff[k][j] = W1[k][j] (j<64) else W1[128+k][j-64]
// Block: 256 threads, 32 rows x 128 cols per block, 4 rows per warp.
// k tiled in 4 chunks of 32. sE2 holds each value duplicated (v,v) so the
// broadcast scalar is already a packed f32x2 operand.
// ---------------------------------------------------------------------------
__global__ void __launch_bounds__(256) pq_gemm_kernel(
    const float* __restrict__ emb,
    const float* __restrict__ W1,
    int num_nodes)
{
    __shared__ float sW[32][128];    // 16KB: W chunk (k x j)
    __shared__ float sE2[32][64];    // 8KB : 32 rows x 32 k, each value duplicated

    const int tid  = threadIdx.x;
    const int warp = tid >> 5;
    const int lane = tid & 31;
    const int row_base = blockIdx.x * 32;

    ull_t acc[4][2];
    #pragma unroll
    for (int r = 0; r < 4; r++) { acc[r][0] = 0ULL; acc[r][1] = 0ULL; }

    for (int kc = 0; kc < 4; kc++) {
        if (kc) __syncthreads();
        // load W chunk: 32 x 128 elements
        for (int i = tid; i < 32 * 128; i += 256) {
            int k = i >> 7;
            int j = i & 127;
            int gk = kc * 32 + k;
            float v = (j < 64) ? W1[gk * 64 + j] : W1[(128 + gk) * 64 + (j - 64)];
            sW[k][j] = v;
        }
        // load emb tile: 32 rows x 32 k, duplicated into float pairs
        for (int i = tid; i < 32 * 16; i += 256) {
            int r  = i >> 4;
            int c2 = i & 15;          // which float2 within the 32-k chunk
            int gr = row_base + r;
            float2 v = make_float2(0.f, 0.f);
            if (gr < num_nodes)
                v = *reinterpret_cast<const float2*>(&emb[(size_t)gr * 128 + kc * 32 + c2 * 2]);
            float4 d = make_float4(v.x, v.x, v.y, v.y);
            *reinterpret_cast<float4*>(&sE2[r][c2 * 4]) = d;
        }
        __syncthreads();

        const int j4 = lane * 4;
        #pragma unroll
        for (int kk = 0; kk < 32; kk += 2) {
            // duplicated e pairs for 2 consecutive k, 4 rows (broadcast LDS.128)
            ulonglong2 e0 = *reinterpret_cast<const ulonglong2*>(&sE2[warp * 4 + 0][kk * 2]);
            ulonglong2 e1 = *reinterpret_cast<const ulonglong2*>(&sE2[warp * 4 + 1][kk * 2]);
            ulonglong2 e2 = *reinterpret_cast<const ulonglong2*>(&sE2[warp * 4 + 2][kk * 2]);
            ulonglong2 e3 = *reinterpret_cast<const ulonglong2*>(&sE2[warp * 4 + 3][kk * 2]);
            // weight pairs for this thread's 4 columns, 2 k values
            ulonglong2 w0 = *reinterpret_cast<const ulonglong2*>(&sW[kk + 0][j4]);
            ulonglong2 w1 = *reinterpret_cast<const ulonglong2*>(&sW[kk + 1][j4]);

            acc[0][0] = ffma2(e0.x, w0.x, acc[0][0]);
            acc[0][1] = ffma2(e0.x, w0.y, acc[0][1]);
            acc[1][0] = ffma2(e1.x, w0.x, acc[1][0]);
            acc[1][1] = ffma2(e1.x, w0.y, acc[1][1]);
            acc[2][0] = ffma2(e2.x, w0.x, acc[2][0]);
            acc[2][1] = ffma2(e2.x, w0.y, acc[2][1]);
            acc[3][0] = ffma2(e3.x, w0.x, acc[3][0]);
            acc[3][1] = ffma2(e3.x, w0.y, acc[3][1]);

            acc[0][0] = ffma2(e0.y, w1.x, acc[0][0]);
            acc[0][1] = ffma2(e0.y, w1.y, acc[0][1]);
            acc[1][0] = ffma2(e1.y, w1.x, acc[1][0]);
            acc[1][1] = ffma2(e1.y, w1.y, acc[1][1]);
            acc[2][0] = ffma2(e2.y, w1.x, acc[2][0]);
            acc[2][1] = ffma2(e2.y, w1.y, acc[2][1]);
            acc[3][0] = ffma2(e3.y, w1.x, acc[3][0]);
            acc[3][1] = ffma2(e3.y, w1.y, acc[3][1]);
        }
    }

    #pragma unroll
    for (int r = 0; r < 4; r++) {
        int gr = row_base + warp * 4 + r;
        if (gr < num_nodes) {
            float2 lo = *reinterpret_cast<const float2*>(&acc[r][0]);
            float2 hi = *reinterpret_cast<const float2*>(&acc[r][1]);
            float4 o  = make_float4(lo.x, lo.y, hi.x, hi.y);
            *reinterpret_cast<float4*>(&g_PQ[(size_t)gr * 128 + lane * 4]) = o;
        }
    }
}

// ---------------------------------------------------------------------------
// Kernel 2: per-edge MLP tail + gumbel-sigmoid
// 16 threads per edge; each thread owns 4 hidden units (float4).
// ---------------------------------------------------------------------------
__global__ void __launch_bounds__(256) edge_kernel(
    const void* __restrict__ eidx_raw,    // [2, E] int32 or int64 (see g_idx_is64)
    const float* __restrict__ u1,
    const float* __restrict__ u2,
    const float* __restrict__ b1,
    const float* __restrict__ W2,
    const float* __restrict__ b2,
    float* __restrict__ out,
    int num_edges)
{
    const int tid = threadIdx.x;
    const int g   = tid >> 4;    // group within block (0..15)
    const int gl  = tid & 15;    // lane within group
    const long long e_raw = (long long)blockIdx.x * 16 + g;
    // Clamp instead of early-return so shuffle groups stay fully active.
    const bool valid = (e_raw < num_edges);
    const long long e = valid ? e_raw : (long long)(num_edges - 1);

    int row, col;
    if (g_idx_is64) {
        const long long* eidx = (const long long*)eidx_raw;
        row = (int)eidx[e];
        col = (int)eidx[(long long)num_edges + e];
    } else {
        const int* eidx = (const int*)eidx_raw;
        row = eidx[e];
        col = eidx[(long long)num_edges + e];
    }
    const int j0 = gl * 4;

    float4 p  = *reinterpret_cast<const float4*>(&g_PQ[(size_t)row * 128 + j0]);
    float4 q  = *reinterpret_cast<const float4*>(&g_PQ[(size_t)col * 128 + 64 + j0]);
    float4 bb = *reinterpret_cast<const float4*>(&b1[j0]);
    float4 w  = *reinterpret_cast<const float4*>(&W2[j0]);

    float h0 = fmaxf(p.x + q.x + bb.x, 0.f);
    float h1 = fmaxf(p.y + q.y + bb.y, 0.f);
    float h2 = fmaxf(p.z + q.z + bb.z, 0.f);
    float h3 = fmaxf(p.w + q.w + bb.w, 0.f);

    float partial = fmaf(h0, w.x, fmaf(h1, w.y, fmaf(h2, w.z, h3 * w.w)));
    #pragma unroll
    for (int o = 8; o >= 1; o >>= 1)
        partial += __shfl_xor_sync(0xffffffffu, partial, o);

    if (gl == 0 && valid) {
        float logit = partial + b2[0];
        // Accurate log/exp: -log(-log(u)) is ill-conditioned near u->1.
        float v1 = fminf(fmaxf(u1[e], EPS_F), 1.0f - EPS_F);
        float v2 = fminf(fmaxf(u2[e], EPS_F), 1.0f - EPS_F);
        float g1 = -logf(-logf(v1));
        float g2 = -logf(-logf(v2));
        float x  = logit + g1 - g2;
        out[e] = 1.0f / (1.0f + expf(-x));
    }
}

// ---------------------------------------------------------------------------
// Inputs (metadata order): node_embed, edge_index, u1, u2, W1, b1, W2, b2
// Output: float32 [num_edges]
// ---------------------------------------------------------------------------
extern "C" void kernel_launch(void* const* d_in, const int* in_sizes, int n_in,
                              void* d_out, int out_size)
{
    const float* node_embed = (const float*)d_in[0];
    const void*  edge_index = d_in[1];
    const float* u1         = (const float*)d_in[2];
    const float* u2         = (const float*)d_in[3];
    const float* W1         = (const float*)d_in[4];
    const float* b1         = (const float*)d_in[5];
    const float* W2         = (const float*)d_in[6];
    const float* b2         = (const float*)d_in[7];
    float*       out        = (float*)d_out;

    const int num_nodes = in_sizes[0] / EMBED;
    const int num_edges = in_sizes[2];

    detect_idx_dtype_kernel<<<1, 32>>>((const int*)edge_index, num_edges);

    int gemm_blocks = (num_nodes + 31) / 32;
    pq_gemm_kernel<<<gemm_blocks, 256>>>(node_embed, W1, num_nodes);

    int edge_blocks = (num_edges + 15) / 16;
    edge_kernel<<<edge_blocks, 256>>>(edge_index, u1, u2, b1, W2, b2, out, num_edges);
}

// round 6
// speedup vs baseline: 1.1009x; 1.1009x over previous
#include <cuda_runtime.h>

#define EMBED      128
#define HID        64
#define MAX_NODES  50000
#define EPS_F      1e-10f

// Scratch: PQ[n][0:64] = node_embed[n] @ W1[0:128], PQ[n][64:128] = node_embed[n] @ W1[128:256]
__device__ float g_PQ[(size_t)MAX_NODES * 128];
// 1 if edge_index buffer is int64 (little-endian), 0 if int32.
__device__ int g_idx_is64;

// ---------------------------------------------------------------------------
// Kernel 1: PQ = node_embed(50000x128) @ W_eff(128x128)
// W_eff[k][j] = W1[k][j] (j<64) else W1[128+k][j-64]
// Block: 256 threads, 32 rows x 128 cols per block, 4 rows per warp.
// k tiled in 2 chunks of 64 (40KB smem total).
// Block 0 / warp 0 additionally detects the edge_index dtype (fused here to
// kill the separate 4.5us detect launch): int64 indices < 2^31 have all-zero
// odd 32-bit words; 32 random int32 indices all being zero is impossible.
// ---------------------------------------------------------------------------
__global__ void __launch_bounds__(256) pq_gemm_kernel(
    const float* __restrict__ emb,
    const float* __restrict__ W1,
    const int*   __restrict__ eidx32,
    int num_nodes, int num_edges)
{
    __shared__ float sW[64][128];   // 32KB
    __shared__ float sE[32][64];    // 8KB

    const int tid  = threadIdx.x;
    const int warp = tid >> 5;
    const int lane = tid & 31;
    const int row_base = blockIdx.x * 32;

    // Fused dtype detection (block 0, warp 0; no sync needed with the rest
    // of this kernel — consumer is the next kernel on the stream).
    if (blockIdx.x == 0 && warp == 0) {
        int i = lane < num_edges ? lane : 0;
        int nz = (eidx32[2 * i + 1] != 0) ? 1 : 0;
        unsigned mask = __ballot_sync(0xffffffffu, nz);
        if (lane == 0) g_idx_is64 = (mask == 0u) ? 1 : 0;
    }

    float4 acc[4];
    #pragma unroll
    for (int r = 0; r < 4; r++) acc[r] = make_float4(0.f, 0.f, 0.f, 0.f);

    const float4 zero4 = make_float4(0.f, 0.f, 0.f, 0.f);

    for (int kc = 0; kc < 2; kc++) {
        if (kc) __syncthreads();
        // load W chunk: 64 x 128 elements
        for (int i = tid; i < 64 * 128; i += 256) {
            int k = i >> 7;
            int j = i & 127;
            int gk = kc * 64 + k;
            float v = (j < 64) ? W1[gk * 64 + j] : W1[(128 + gk) * 64 + (j - 64)];
            sW[k][j] = v;
        }
        // load emb tile: 32 rows x 64 cols (as float4)
        for (int i = tid; i < 32 * 16; i += 256) {
            int r  = i >> 4;
            int c4 = i & 15;
            int gr = row_base + r;
            float4 v = zero4;
            if (gr < num_nodes)
                v = *reinterpret_cast<const float4*>(&emb[(size_t)gr * 128 + kc * 64 + c4 * 4]);
            *reinterpret_cast<float4*>(&sE[r][c4 * 4]) = v;
        }
        __syncthreads();

        const int j4 = lane * 4;
        #pragma unroll
        for (int kk = 0; kk < 64; kk += 4) {
            float4 e0 = *reinterpret_cast<const float4*>(&sE[warp * 4 + 0][kk]);
            float4 e1 = *reinterpret_cast<const float4*>(&sE[warp * 4 + 1][kk]);
            float4 e2 = *reinterpret_cast<const float4*>(&sE[warp * 4 + 2][kk]);
            float4 e3 = *reinterpret_cast<const float4*>(&sE[warp * 4 + 3][kk]);
            #define FMA4(A, S, W) \
                (A).x = fmaf((S), (W).x, (A).x); \
                (A).y = fmaf((S), (W).y, (A).y); \
                (A).z = fmaf((S), (W).z, (A).z); \
                (A).w = fmaf((S), (W).w, (A).w);
            {
                float4 w = *reinterpret_cast<const float4*>(&sW[kk + 0][j4]);
                FMA4(acc[0], e0.x, w); FMA4(acc[1], e1.x, w);
                FMA4(acc[2], e2.x, w); FMA4(acc[3], e3.x, w);
            }
            {
                float4 w = *reinterpret_cast<const float4*>(&sW[kk + 1][j4]);
                FMA4(acc[0], e0.y, w); FMA4(acc[1], e1.y, w);
                FMA4(acc[2], e2.y, w); FMA4(acc[3], e3.y, w);
            }
            {
                float4 w = *reinterpret_cast<const float4*>(&sW[kk + 2][j4]);
                FMA4(acc[0], e0.z, w); FMA4(acc[1], e1.z, w);
                FMA4(acc[2], e2.z, w); FMA4(acc[3], e3.z, w);
            }
            {
                float4 w = *reinterpret_cast<const float4*>(&sW[kk + 3][j4]);
                FMA4(acc[0], e0.w, w); FMA4(acc[1], e1.w, w);
                FMA4(acc[2], e2.w, w); FMA4(acc[3], e3.w, w);
            }
            #undef FMA4
        }
    }

    #pragma unroll
    for (int r = 0; r < 4; r++) {
        int gr = row_base + warp * 4 + r;
        if (gr < num_nodes)
            *reinterpret_cast<float4*>(&g_PQ[(size_t)gr * 128 + lane * 4]) = acc[r];
    }
}

// ---------------------------------------------------------------------------
// Kernel 2: per-edge MLP tail + gumbel-sigmoid
// 16 threads per edge; each thread owns 4 hidden units (float4).
// ---------------------------------------------------------------------------
__global__ void __launch_bounds__(256) edge_kernel(
    const void* __restrict__ eidx_raw,    // [2, E] int32 or int64 (see g_idx_is64)
    const float* __restrict__ u1,
    const float* __restrict__ u2,
    const float* __restrict__ b1,
    const float* __restrict__ W2,
    const float* __restrict__ b2,
    float* __restrict__ out,
    int num_edges)
{
    const int tid = threadIdx.x;
    const int g   = tid >> 4;    // group within block (0..15)
    const int gl  = tid & 15;    // lane within group
    const long long e_raw = (long long)blockIdx.x * 16 + g;
    // Clamp instead of early-return so shuffle groups stay fully active.
    const bool valid = (e_raw < num_edges);
    const long long e = valid ? e_raw : (long long)(num_edges - 1);

    int row, col;
    if (g_idx_is64) {
        const long long* eidx = (const long long*)eidx_raw;
        row = (int)eidx[e];
        col = (int)eidx[(long long)num_edges + e];
    } else {
        const int* eidx = (const int*)eidx_raw;
        row = eidx[e];
        col = eidx[(long long)num_edges + e];
    }
    const int j0 = gl * 4;

    float4 p  = *reinterpret_cast<const float4*>(&g_PQ[(size_t)row * 128 + j0]);
    float4 q  = *reinterpret_cast<const float4*>(&g_PQ[(size_t)col * 128 + 64 + j0]);
    float4 bb = *reinterpret_cast<const float4*>(&b1[j0]);
    float4 w  = *reinterpret_cast<const float4*>(&W2[j0]);

    float h0 = fmaxf(p.x + q.x + bb.x, 0.f);
    float h1 = fmaxf(p.y + q.y + bb.y, 0.f);
    float h2 = fmaxf(p.z + q.z + bb.z, 0.f);
    float h3 = fmaxf(p.w + q.w + bb.w, 0.f);

    float partial = fmaf(h0, w.x, fmaf(h1, w.y, fmaf(h2, w.z, h3 * w.w)));
    #pragma unroll
    for (int o = 8; o >= 1; o >>= 1)
        partial += __shfl_xor_sync(0xffffffffu, partial, o);

    if (gl == 0 && valid) {
        float logit = partial + b2[0];
        // Accurate log/exp: -log(-log(u)) is ill-conditioned near u->1,
        // and MUFU __logf absolute error blows up the Gumbel for u close to 1.
        float v1 = fminf(fmaxf(u1[e], EPS_F), 1.0f - EPS_F);
        float v2 = fminf(fmaxf(u2[e], EPS_F), 1.0f - EPS_F);
        float g1 = -logf(-logf(v1));
        float g2 = -logf(-logf(v2));
        float x  = logit + g1 - g2;
        out[e] = 1.0f / (1.0f + expf(-x));
    }
}

// ---------------------------------------------------------------------------
// Inputs (metadata order): node_embed, edge_index, u1, u2, W1, b1, W2, b2
// Output: float32 [num_edges]
// ---------------------------------------------------------------------------
extern "C" void kernel_launch(void* const* d_in, const int* in_sizes, int n_in,
                              void* d_out, int out_size)
{
    const float* node_embed = (const float*)d_in[0];
    const void*  edge_index = d_in[1];
    const float* u1         = (const float*)d_in[2];
    const float* u2         = (const float*)d_in[3];
    const float* W1         = (const float*)d_in[4];
    const float* b1         = (const float*)d_in[5];
    const float* W2         = (const float*)d_in[6];
    const float* b2         = (const float*)d_in[7];
    float*       out        = (float*)d_out;

    const int num_nodes = in_sizes[0] / EMBED;
    const int num_edges = in_sizes[2];

    int gemm_blocks = (num_nodes + 31) / 32;
    pq_gemm_kernel<<<gemm_blocks, 256>>>(node_embed, W1, (const int*)edge_index,
                                         num_nodes, num_edges);

    int edge_blocks = (num_edges + 15) / 16;
    edge_kernel<<<edge_blocks, 256>>>(edge_index, u1, u2, b1, W2, b2, out, num_edges);
}

// round 7
// speedup vs baseline: 1.2640x; 1.1482x over previous
#include <cuda_runtime.h>

#define EMBED      128
#define HID        64
#define MAX_NODES  50000
#define EPS_F      1e-10f

// Scratch: PQ[n][0:64] = P = emb[n] @ W1[0:128];
//          PQ[n][64:128] = Q+b1 = emb[n] @ W1[128:256] + b1  (b1 folded in epilogue)
__device__ float g_PQ[(size_t)MAX_NODES * 128];
// 1 if edge_index buffer is int64 (little-endian), 0 if int32.
__device__ int g_idx_is64;

// ---------------------------------------------------------------------------
// Kernel 1: PQ = node_embed(50000x128) @ W_eff(128x128)  (+ b1 on cols 64..127)
// W_eff[k][j] = W1[k][j] (j<64) else W1[128+k][j-64]
// Block: 256 threads, 32 rows x 128 cols per block, 4 rows per warp.
// Block 0 / warp 0 additionally detects the edge_index dtype (fused; int64
// indices < 2^31 have all-zero odd 32-bit words).
// ---------------------------------------------------------------------------
__global__ void __launch_bounds__(256) pq_gemm_kernel(
    const float* __restrict__ emb,
    const float* __restrict__ W1,
    const float* __restrict__ b1,
    const int*   __restrict__ eidx32,
    int num_nodes, int num_edges)
{
    __shared__ float sW[64][128];   // 32KB
    __shared__ float sE[32][64];    // 8KB

    const int tid  = threadIdx.x;
    const int warp = tid >> 5;
    const int lane = tid & 31;
    const int row_base = blockIdx.x * 32;

    if (blockIdx.x == 0 && warp == 0) {
        int i = lane < num_edges ? lane : 0;
        int nz = (eidx32[2 * i + 1] != 0) ? 1 : 0;
        unsigned mask = __ballot_sync(0xffffffffu, nz);
        if (lane == 0) g_idx_is64 = (mask == 0u) ? 1 : 0;
    }

    float4 acc[4];
    #pragma unroll
    for (int r = 0; r < 4; r++) acc[r] = make_float4(0.f, 0.f, 0.f, 0.f);

    const float4 zero4 = make_float4(0.f, 0.f, 0.f, 0.f);

    for (int kc = 0; kc < 2; kc++) {
        if (kc) __syncthreads();
        for (int i = tid; i < 64 * 128; i += 256) {
            int k = i >> 7;
            int j = i & 127;
            int gk = kc * 64 + k;
            float v = (j < 64) ? W1[gk * 64 + j] : W1[(128 + gk) * 64 + (j - 64)];
            sW[k][j] = v;
        }
        for (int i = tid; i < 32 * 16; i += 256) {
            int r  = i >> 4;
            int c4 = i & 15;
            int gr = row_base + r;
            float4 v = zero4;
            if (gr < num_nodes)
                v = *reinterpret_cast<const float4*>(&emb[(size_t)gr * 128 + kc * 64 + c4 * 4]);
            *reinterpret_cast<float4*>(&sE[r][c4 * 4]) = v;
        }
        __syncthreads();

        const int j4 = lane * 4;
        #pragma unroll
        for (int kk = 0; kk < 64; kk += 4) {
            float4 e0 = *reinterpret_cast<const float4*>(&sE[warp * 4 + 0][kk]);
            float4 e1 = *reinterpret_cast<const float4*>(&sE[warp * 4 + 1][kk]);
            float4 e2 = *reinterpret_cast<const float4*>(&sE[warp * 4 + 2][kk]);
            float4 e3 = *reinterpret_cast<const float4*>(&sE[warp * 4 + 3][kk]);
            #define FMA4(A, S, W) \
                (A).x = fmaf((S), (W).x, (A).x); \
                (A).y = fmaf((S), (W).y, (A).y); \
                (A).z = fmaf((S), (W).z, (A).z); \
                (A).w = fmaf((S), (W).w, (A).w);
            {
                float4 w = *reinterpret_cast<const float4*>(&sW[kk + 0][j4]);
                FMA4(acc[0], e0.x, w); FMA4(acc[1], e1.x, w);
                FMA4(acc[2], e2.x, w); FMA4(acc[3], e3.x, w);
            }
            {
                float4 w = *reinterpret_cast<const float4*>(&sW[kk + 1][j4]);
                FMA4(acc[0], e0.y, w); FMA4(acc[1], e1.y, w);
                FMA4(acc[2], e2.y, w); FMA4(acc[3], e3.y, w);
            }
            {
                float4 w = *reinterpret_cast<const float4*>(&sW[kk + 2][j4]);
                FMA4(acc[0], e0.z, w); FMA4(acc[1], e1.z, w);
                FMA4(acc[2], e2.z, w); FMA4(acc[3], e3.z, w);
            }
            {
                float4 w = *reinterpret_cast<const float4*>(&sW[kk + 3][j4]);
                FMA4(acc[0], e0.w, w); FMA4(acc[1], e1.w, w);
                FMA4(acc[2], e2.w, w); FMA4(acc[3], e3.w, w);
            }
            #undef FMA4
        }
    }

    // Fold b1 into the Q half (columns 64..127 <=> lane >= 16).
    float4 badd = zero4;
    if (lane >= 16)
        badd = *reinterpret_cast<const float4*>(&b1[(lane - 16) * 4]);

    #pragma unroll
    for (int r = 0; r < 4; r++) {
        int gr = row_base + warp * 4 + r;
        if (gr < num_nodes) {
            float4 o = acc[r];
            o.x += badd.x; o.y += badd.y; o.z += badd.z; o.w += badd.w;
            *reinterpret_cast<float4*>(&g_PQ[(size_t)gr * 128 + lane * 4]) = o;
        }
    }
}

// log(v) for v in (0,1]: MUFU __logf except near 1, where log1p polynomial
// fixes the absolute-error blowup of MUFU (needed because -log(v) ~ (1-v)).
__device__ __forceinline__ float fast_log01(float v)
{
    float t = v - 1.0f;   // |t| small when v near 1
    // log(1+t) = t(1 - t/2 + t^2/3 - t^3/4 + t^4/5), |err| <= |t|^5/6
    float p = 1.0f + t * (-0.5f + t * (0.33333333f + t * (-0.25f + t * 0.2f)));
    p *= t;
    float m = __logf(v);
    return (v > 0.9375f) ? p : m;
}

// ---------------------------------------------------------------------------
// Kernel 2: per-edge MLP tail + fused gumbel-sigmoid.
// 4 threads per edge; each lane owns 16 hidden units.
//   out = L2 / (L2 + exp(-logit)*L1),  L = -log(u)   [algebraically identical
//   to sigmoid(logit - log L1 + log L2)]
// ---------------------------------------------------------------------------
__global__ void __launch_bounds__(256) edge_kernel(
    const void* __restrict__ eidx_raw,    // [2, E] int32 or int64 (see g_idx_is64)
    const float* __restrict__ u1,
    const float* __restrict__ u2,
    const float* __restrict__ W2,
    const float* __restrict__ b2,
    float* __restrict__ out,
    int num_edges)
{
    const int tid = threadIdx.x;
    const int g   = tid >> 2;    // edge slot within block (0..63)
    const int gl  = tid & 3;     // lane within edge
    const long long e_raw = (long long)blockIdx.x * 64 + g;
    const bool valid = (e_raw < num_edges);
    const long long e = valid ? e_raw : (long long)(num_edges - 1);

    int row, col;
    if (g_idx_is64) {
        const long long* eidx = (const long long*)eidx_raw;
        row = (int)eidx[e];
        col = (int)eidx[(long long)num_edges + e];
    } else {
        const int* eidx = (const int*)eidx_raw;
        row = eidx[e];
        col = eidx[(long long)num_edges + e];
    }

    const float* pbase = g_PQ + row * 128 + gl * 16;
    const float* qbase = g_PQ + col * 128 + 64 + gl * 16;
    const float* wbase = W2 + gl * 16;

    float partial = 0.0f;
    #pragma unroll
    for (int i = 0; i < 4; i++) {
        float4 p = *reinterpret_cast<const float4*>(pbase + i * 4);
        float4 q = *reinterpret_cast<const float4*>(qbase + i * 4);
        float4 w = *reinterpret_cast<const float4*>(wbase + i * 4);
        partial = fmaf(fmaxf(p.x + q.x, 0.f), w.x, partial);
        partial = fmaf(fmaxf(p.y + q.y, 0.f), w.y, partial);
        partial = fmaf(fmaxf(p.z + q.z, 0.f), w.z, partial);
        partial = fmaf(fmaxf(p.w + q.w, 0.f), w.w, partial);
    }
    partial += __shfl_xor_sync(0xffffffffu, partial, 1);
    partial += __shfl_xor_sync(0xffffffffu, partial, 2);

    if (gl == 0 && valid) {
        float logit = partial + b2[0];
        float v1 = fminf(fmaxf(u1[e], EPS_F), 1.0f - EPS_F);
        float v2 = fminf(fmaxf(u2[e], EPS_F), 1.0f - EPS_F);
        float L1 = -fast_log01(v1);
        float L2 = -fast_log01(v2);
        float t  = __expf(-logit) * L1;
        out[e] = __fdividef(L2, L2 + t);
    }
}

// ---------------------------------------------------------------------------
// Inputs (metadata order): node_embed, edge_index, u1, u2, W1, b1, W2, b2
// Output: float32 [num_edges]
// ---------------------------------------------------------------------------
extern "C" void kernel_launch(void* const* d_in, const int* in_sizes, int n_in,
                              void* d_out, int out_size)
{
    const float* node_embed = (const float*)d_in[0];
    const void*  edge_index = d_in[1];
    const float* u1         = (const float*)d_in[2];
    const float* u2         = (const float*)d_in[3];
    const float* W1         = (const float*)d_in[4];
    const float* b1         = (const float*)d_in[5];
    const float* W2         = (const float*)d_in[6];
    const float* b2         = (const float*)d_in[7];
    float*       out        = (float*)d_out;

    const int num_nodes = in_sizes[0] / EMBED;
    const int num_edges = in_sizes[2];

    int gemm_blocks = (num_nodes + 31) / 32;
    pq_gemm_kernel<<<gemm_blocks, 256>>>(node_embed, W1, b1, (const int*)edge_index,
                                         num_nodes, num_edges);

    int edge_blocks = (num_edges + 63) / 64;
    edge_kernel<<<edge_blocks, 256>>>(edge_index, u1, u2, W2, b2, out, num_edges);
}

// round 8
// speedup vs baseline: 1.5420x; 1.2199x over previous
#include <cuda_runtime.h>

#define EMBED      128
#define HID        64
#define MAX_NODES  50000
#define EPS_F      1e-10f

// Scratch: PQ[n][0:64] = P = emb[n] @ W1[0:128];
//          PQ[n][64:128] = Q+b1 = emb[n] @ W1[128:256] + b1  (b1 folded in epilogue)
__device__ float g_PQ[(size_t)MAX_NODES * 128];
// 1 if edge_index buffer is int64 (little-endian), 0 if int32.
__device__ int g_idx_is64;

// ---------------------------------------------------------------------------
// Kernel 1: PQ = node_embed(50000x128) @ W_eff(128x128)  (+ b1 on cols 64..127)
// W_eff[k][j] = W1[k][j] (j<64) else W1[128+k][j-64]
// Block: 256 threads, 32 rows x 128 cols per block, 4 rows per warp.
// Block 0 / warp 0 additionally detects the edge_index dtype (fused; int64
// indices < 2^31 have all-zero odd 32-bit words).
// ---------------------------------------------------------------------------
__global__ void __launch_bounds__(256) pq_gemm_kernel(
    const float* __restrict__ emb,
    const float* __restrict__ W1,
    const float* __restrict__ b1,
    const int*   __restrict__ eidx32,
    int num_nodes, int num_edges)
{
    __shared__ float sW[64][128];   // 32KB
    __shared__ float sE[32][64];    // 8KB

    const int tid  = threadIdx.x;
    const int warp = tid >> 5;
    const int lane = tid & 31;
    const int row_base = blockIdx.x * 32;

    if (blockIdx.x == 0 && warp == 0) {
        int i = lane < num_edges ? lane : 0;
        int nz = (eidx32[2 * i + 1] != 0) ? 1 : 0;
        unsigned mask = __ballot_sync(0xffffffffu, nz);
        if (lane == 0) g_idx_is64 = (mask == 0u) ? 1 : 0;
    }

    float4 acc[4];
    #pragma unroll
    for (int r = 0; r < 4; r++) acc[r] = make_float4(0.f, 0.f, 0.f, 0.f);

    const float4 zero4 = make_float4(0.f, 0.f, 0.f, 0.f);

    for (int kc = 0; kc < 2; kc++) {
        if (kc) __syncthreads();
        for (int i = tid; i < 64 * 128; i += 256) {
            int k = i >> 7;
            int j = i & 127;
            int gk = kc * 64 + k;
            float v = (j < 64) ? W1[gk * 64 + j] : W1[(128 + gk) * 64 + (j - 64)];
            sW[k][j] = v;
        }
        for (int i = tid; i < 32 * 16; i += 256) {
            int r  = i >> 4;
            int c4 = i & 15;
            int gr = row_base + r;
            float4 v = zero4;
            if (gr < num_nodes)
                v = *reinterpret_cast<const float4*>(&emb[(size_t)gr * 128 + kc * 64 + c4 * 4]);
            *reinterpret_cast<float4*>(&sE[r][c4 * 4]) = v;
        }
        __syncthreads();

        const int j4 = lane * 4;
        #pragma unroll
        for (int kk = 0; kk < 64; kk += 4) {
            float4 e0 = *reinterpret_cast<const float4*>(&sE[warp * 4 + 0][kk]);
            float4 e1 = *reinterpret_cast<const float4*>(&sE[warp * 4 + 1][kk]);
            float4 e2 = *reinterpret_cast<const float4*>(&sE[warp * 4 + 2][kk]);
            float4 e3 = *reinterpret_cast<const float4*>(&sE[warp * 4 + 3][kk]);
            #define FMA4(A, S, W) \
                (A).x = fmaf((S), (W).x, (A).x); \
                (A).y = fmaf((S), (W).y, (A).y); \
                (A).z = fmaf((S), (W).z, (A).z); \
                (A).w = fmaf((S), (W).w, (A).w);
            {
                float4 w = *reinterpret_cast<const float4*>(&sW[kk + 0][j4]);
                FMA4(acc[0], e0.x, w); FMA4(acc[1], e1.x, w);
                FMA4(acc[2], e2.x, w); FMA4(acc[3], e3.x, w);
            }
            {
                float4 w = *reinterpret_cast<const float4*>(&sW[kk + 1][j4]);
                FMA4(acc[0], e0.y, w); FMA4(acc[1], e1.y, w);
                FMA4(acc[2], e2.y, w); FMA4(acc[3], e3.y, w);
            }
            {
                float4 w = *reinterpret_cast<const float4*>(&sW[kk + 2][j4]);
                FMA4(acc[0], e0.z, w); FMA4(acc[1], e1.z, w);
                FMA4(acc[2], e2.z, w); FMA4(acc[3], e3.z, w);
            }
            {
                float4 w = *reinterpret_cast<const float4*>(&sW[kk + 3][j4]);
                FMA4(acc[0], e0.w, w); FMA4(acc[1], e1.w, w);
                FMA4(acc[2], e2.w, w); FMA4(acc[3], e3.w, w);
            }
            #undef FMA4
        }
    }

    // Fold b1 into the Q half (columns 64..127 <=> lane >= 16).
    float4 badd = zero4;
    if (lane >= 16)
        badd = *reinterpret_cast<const float4*>(&b1[(lane - 16) * 4]);

    #pragma unroll
    for (int r = 0; r < 4; r++) {
        int gr = row_base + warp * 4 + r;
        if (gr < num_nodes) {
            float4 o = acc[r];
            o.x += badd.x; o.y += badd.y; o.z += badd.z; o.w += badd.w;
            *reinterpret_cast<float4*>(&g_PQ[(size_t)gr * 128 + lane * 4]) = o;
        }
    }
}

// log(v) for v in (0,1]: MUFU __logf except near 1, where log1p polynomial
// fixes the absolute-error blowup of MUFU (needed because -log(v) ~ (1-v)).
__device__ __forceinline__ float fast_log01(float v)
{
    float t = v - 1.0f;   // |t| small when v near 1
    float p = 1.0f + t * (-0.5f + t * (0.33333333f + t * (-0.25f + t * 0.2f)));
    p *= t;
    float m = __logf(v);
    return (v > 0.9375f) ? p : m;
}

// ---------------------------------------------------------------------------
// Kernel 2: per-edge MLP tail + fused gumbel-sigmoid.
// 8 threads per edge; lane gl owns interleaved float4 chunks {i*32+gl*4}.
// Each LDG.128 covers exactly one 128B line per edge (L1 wavefront floor:
// 2 lines per 256B half). W2/b2 served from smem.
//   out = L2 / (L2 + exp(-logit)*L1),  L = -log(u)
// ---------------------------------------------------------------------------
__global__ void __launch_bounds__(256) edge_kernel(
    const void* __restrict__ eidx_raw,    // [2, E] int32 or int64 (see g_idx_is64)
    const float* __restrict__ u1,
    const float* __restrict__ u2,
    const float* __restrict__ W2,
    const float* __restrict__ b2,
    float* __restrict__ out,
    int num_edges)
{
    __shared__ float sW2[HID];
    __shared__ float sb2;

    const int tid = threadIdx.x;
    if (tid < HID) sW2[tid] = W2[tid];
    if (tid == HID) sb2 = b2[0];
    __syncthreads();

    const int g   = tid >> 3;    // edge slot within block (0..31)
    const int gl  = tid & 7;     // lane within edge
    const long long e_raw = (long long)blockIdx.x * 32 + g;
    const bool valid = (e_raw < num_edges);
    const long long e = valid ? e_raw : (long long)(num_edges - 1);

    int row, col;
    if (g_idx_is64) {
        const long long* eidx = (const long long*)eidx_raw;
        row = (int)eidx[e];
        col = (int)eidx[(long long)num_edges + e];
    } else {
        const int* eidx = (const int*)eidx_raw;
        row = eidx[e];
        col = eidx[(long long)num_edges + e];
    }

    const float* pbase = g_PQ + row * 128;
    const float* qbase = g_PQ + col * 128 + 64;

    float partial = 0.0f;
    #pragma unroll
    for (int i = 0; i < 2; i++) {
        const int off = i * 32 + gl * 4;   // 8 lanes x 16B = one 128B line per edge
        float4 p = *reinterpret_cast<const float4*>(pbase + off);
        float4 q = *reinterpret_cast<const float4*>(qbase + off);
        float4 w = *reinterpret_cast<const float4*>(&sW2[off]);
        partial = fmaf(fmaxf(p.x + q.x, 0.f), w.x, partial);
        partial = fmaf(fmaxf(p.y + q.y, 0.f), w.y, partial);
        partial = fmaf(fmaxf(p.z + q.z, 0.f), w.z, partial);
        partial = fmaf(fmaxf(p.w + q.w, 0.f), w.w, partial);
    }
    partial += __shfl_xor_sync(0xffffffffu, partial, 1);
    partial += __shfl_xor_sync(0xffffffffu, partial, 2);
    partial += __shfl_xor_sync(0xffffffffu, partial, 4);

    if (gl == 0 && valid) {
        float logit = partial + sb2;
        float v1 = fminf(fmaxf(u1[e], EPS_F), 1.0f - EPS_F);
        float v2 = fminf(fmaxf(u2[e], EPS_F), 1.0f - EPS_F);
        float L1 = -fast_log01(v1);
        float L2 = -fast_log01(v2);
        float t  = __expf(-logit) * L1;
        out[e] = __fdividef(L2, L2 + t);
    }
}

// ---------------------------------------------------------------------------
// Inputs (metadata order): node_embed, edge_index, u1, u2, W1, b1, W2, b2
// Output: float32 [num_edges]
// ---------------------------------------------------------------------------
extern "C" void kernel_launch(void* const* d_in, const int* in_sizes, int n_in,
                              void* d_out, int out_size)
{
    const float* node_embed = (const float*)d_in[0];
    const void*  edge_index = d_in[1];
    const float* u1         = (const float*)d_in[2];
    const float* u2         = (const float*)d_in[3];
    const float* W1         = (const float*)d_in[4];
    const float* b1         = (const float*)d_in[5];
    const float* W2         = (const float*)d_in[6];
    const float* b2         = (const float*)d_in[7];
    float*       out        = (float*)d_out;

    const int num_nodes = in_sizes[0] / EMBED;
    const int num_edges = in_sizes[2];

    int gemm_blocks = (num_nodes + 31) / 32;
    pq_gemm_kernel<<<gemm_blocks, 256>>>(node_embed, W1, b1, (const int*)edge_index,
                                         num_nodes, num_edges);

    int edge_blocks = (num_edges + 31) / 32;
    edge_kernel<<<edge_blocks, 256>>>(edge_index, u1, u2, W2, b2, out, num_edges);
}

// round 10
// speedup vs baseline: 1.6714x; 1.0839x over previous
#include <cuda_runtime.h>
#include <cuda_fp16.h>
#include <cstdint>

#define EMBED      128
#define HID        64
#define MAX_NODES  50000
#define EPS_F      1e-10f

// PQ in fp16: PQh[n][0:64] = P = emb[n] @ W1[0:128];
//             PQh[n][64:128] = Q+b1 = emb[n] @ W1[128:256] + b1
// One 64-value half = 128 bytes = exactly one L1 line.
__device__ __half g_PQh[(size_t)MAX_NODES * 128];
__device__ int g_idx_is64;

// ---------------------------------------------------------------------------
// Kernel 1: PQ = node_embed(50000x128) @ W_eff(128x128)  (+ b1 on cols 64..127)
// Scalar-FFMA tiled GEMM (proven at the fp32 roofline); fp16 epilogue.
// Block: 256 threads, 32 rows x 128 cols, 4 rows per warp, k in 2 chunks of 64.
// Block 0 / warp 0 also detects edge_index dtype (int64 indices < 2^31 have
// all-zero odd 32-bit words; 32 random int32 all-zero is impossible).
// ---------------------------------------------------------------------------
__global__ void __launch_bounds__(256) pq_gemm_kernel(
    const float* __restrict__ emb,
    const float* __restrict__ W1,
    const float* __restrict__ b1,
    const int*   __restrict__ eidx32,
    int num_nodes, int num_edges)
{
    __shared__ float sW[64][128];   // 32KB
    __shared__ float sE[32][64];    // 8KB

    const int tid  = threadIdx.x;
    const int warp = tid >> 5;
    const int lane = tid & 31;
    const int row_base = blockIdx.x * 32;

    if (blockIdx.x == 0 && warp == 0) {
        int i = lane < num_edges ? lane : 0;
        int nz = (eidx32[2 * i + 1] != 0) ? 1 : 0;
        unsigned mask = __ballot_sync(0xffffffffu, nz);
        if (lane == 0) g_idx_is64 = (mask == 0u) ? 1 : 0;
    }

    float4 acc[4];
    #pragma unroll
    for (int r = 0; r < 4; r++) acc[r] = make_float4(0.f, 0.f, 0.f, 0.f);

    const float4 zero4 = make_float4(0.f, 0.f, 0.f, 0.f);

    for (int kc = 0; kc < 2; kc++) {
        if (kc) __syncthreads();
        for (int i = tid; i < 64 * 128; i += 256) {
            int k = i >> 7;
            int j = i & 127;
            int gk = kc * 64 + k;
            float v = (j < 64) ? W1[gk * 64 + j] : W1[(128 + gk) * 64 + (j - 64)];
            sW[k][j] = v;
        }
        for (int i = tid; i < 32 * 16; i += 256) {
            int r  = i >> 4;
            int c4 = i & 15;
            int gr = row_base + r;
            float4 v = zero4;
            if (gr < num_nodes)
                v = *reinterpret_cast<const float4*>(&emb[(size_t)gr * 128 + kc * 64 + c4 * 4]);
            *reinterpret_cast<float4*>(&sE[r][c4 * 4]) = v;
        }
        __syncthreads();

        const int j4 = lane * 4;
        #pragma unroll
        for (int kk = 0; kk < 64; kk += 4) {
            float4 e0 = *reinterpret_cast<const float4*>(&sE[warp * 4 + 0][kk]);
            float4 e1 = *reinterpret_cast<const float4*>(&sE[warp * 4 + 1][kk]);
            float4 e2 = *reinterpret_cast<const float4*>(&sE[warp * 4 + 2][kk]);
            float4 e3 = *reinterpret_cast<const float4*>(&sE[warp * 4 + 3][kk]);
            #define FMA4(A, S, W) \
                (A).x = fmaf((S), (W).x, (A).x); \
                (A).y = fmaf((S), (W).y, (A).y); \
                (A).z = fmaf((S), (W).z, (A).z); \
                (A).w = fmaf((S), (W).w, (A).w);
            {
                float4 w = *reinterpret_cast<const float4*>(&sW[kk + 0][j4]);
                FMA4(acc[0], e0.x, w); FMA4(acc[1], e1.x, w);
                FMA4(acc[2], e2.x, w); FMA4(acc[3], e3.x, w);
            }
            {
                float4 w = *reinterpret_cast<const float4*>(&sW[kk + 1][j4]);
                FMA4(acc[0], e0.y, w); FMA4(acc[1], e1.y, w);
                FMA4(acc[2], e2.y, w); FMA4(acc[3], e3.y, w);
            }
            {
                float4 w = *reinterpret_cast<const float4*>(&sW[kk + 2][j4]);
                FMA4(acc[0], e0.z, w); FMA4(acc[1], e1.z, w);
                FMA4(acc[2], e2.z, w); FMA4(acc[3], e3.z, w);
            }
            {
                float4 w = *reinterpret_cast<const float4*>(&sW[kk + 3][j4]);
                FMA4(acc[0], e0.w, w); FMA4(acc[1], e1.w, w);
                FMA4(acc[2], e2.w, w); FMA4(acc[3], e3.w, w);
            }
            #undef FMA4
        }
    }

    // Fold b1 into the Q half (columns 64..127 <=> lane >= 16), store fp16.
    float4 badd = zero4;
    if (lane >= 16)
        badd = *reinterpret_cast<const float4*>(&b1[(lane - 16) * 4]);

    #pragma unroll
    for (int r = 0; r < 4; r++) {
        int gr = row_base + warp * 4 + r;
        if (gr < num_nodes) {
            float4 o = acc[r];
            o.x += badd.x; o.y += badd.y; o.z += badd.z; o.w += badd.w;
            __half2 h01 = __floats2half2_rn(o.x, o.y);
            __half2 h23 = __floats2half2_rn(o.z, o.w);
            uint2 st = make_uint2(*reinterpret_cast<uint32_t*>(&h01),
                                  *reinterpret_cast<uint32_t*>(&h23));
            *reinterpret_cast<uint2*>(&g_PQh[(size_t)gr * 128 + lane * 4]) = st;
        }
    }
}

// log(v) for v in (0,1]: MUFU __logf except near 1 (log1p polynomial fixes
// MUFU absolute-error blowup where -log(v) ~ (1-v)).
__device__ __forceinline__ float fast_log01(float v)
{
    float t = v - 1.0f;
    float p = 1.0f + t * (-0.5f + t * (0.33333333f + t * (-0.25f + t * 0.2f)));
    p *= t;
    float m = __logf(v);
    return (v > 0.9375f) ? p : m;
}

// ---------------------------------------------------------------------------
// Kernel 2: per-edge MLP tail + fused gumbel-sigmoid, fp16 data path.
// 8 lanes/edge; lane gl loads halfs [gl*8, gl*8+8) of each 64-half block:
// one LDG.128 per edge-half across the group = one 128B line (L1 floor).
// h = relu(p+q) and the dot with W2 run as half2 ops; fp32 reduce + tail.
//   out = L2 / (L2 + exp(-logit)*L1),  L = -log(u)
// ---------------------------------------------------------------------------
__global__ void __launch_bounds__(256) edge_kernel(
    const void* __restrict__ eidx_raw,
    const float* __restrict__ u1,
    const float* __restrict__ u2,
    const float* __restrict__ W2,
    const float* __restrict__ b2,
    float* __restrict__ out,
    int num_edges)
{
    __shared__ __half2 sW2h[HID / 2];
    __shared__ float sb2;

    const int tid = threadIdx.x;
    if (tid < HID / 2)
        sW2h[tid] = __floats2half2_rn(W2[2 * tid], W2[2 * tid + 1]);
    if (tid == HID / 2) sb2 = b2[0];
    __syncthreads();

    const int g   = tid >> 3;    // edge slot within block (0..31)
    const int gl  = tid & 7;     // lane within edge
    const long long e_raw = (long long)blockIdx.x * 32 + g;
    const bool valid = (e_raw < num_edges);
    const long long e = valid ? e_raw : (long long)(num_edges - 1);

    int row, col;
    if (g_idx_is64) {
        const long long* eidx = (const long long*)eidx_raw;
        row = (int)eidx[e];
        col = (int)eidx[(long long)num_edges + e];
    } else {
        const int* eidx = (const int*)eidx_raw;
        row = eidx[e];
        col = eidx[(long long)num_edges + e];
    }

    // 8 halfs (16B) per lane; 8 lanes cover the full 128B half-row.
    const uint4 pv = *reinterpret_cast<const uint4*>(&g_PQh[(size_t)row * 128 + gl * 8]);
    const uint4 qv = *reinterpret_cast<const uint4*>(&g_PQh[(size_t)col * 128 + 64 + gl * 8]);
    const uint4 wv = *reinterpret_cast<const uint4*>(&sW2h[gl * 4]);

    const __half2* p2 = reinterpret_cast<const __half2*>(&pv);
    const __half2* q2 = reinterpret_cast<const __half2*>(&qv);
    const __half2* w2 = reinterpret_cast<const __half2*>(&wv);

    const __half2 z2 = __float2half2_rn(0.f);
    __half2 acc2 = z2;
    #pragma unroll
    for (int i = 0; i < 4; i++) {
        __half2 h = __hmax2(__hadd2(p2[i], q2[i]), z2);
        acc2 = __hfma2(h, w2[i], acc2);
    }
    float2 f = __half22float2(acc2);
    float partial = f.x + f.y;
    partial += __shfl_xor_sync(0xffffffffu, partial, 1);
    partial += __shfl_xor_sync(0xffffffffu, partial, 2);
    partial += __shfl_xor_sync(0xffffffffu, partial, 4);

    if (gl == 0 && valid) {
        float logit = partial + sb2;
        float v1 = fminf(fmaxf(u1[e], EPS_F), 1.0f - EPS_F);
        float v2 = fminf(fmaxf(u2[e], EPS_F), 1.0f - EPS_F);
        float L1 = -fast_log01(v1);
        float L2 = -fast_log01(v2);
        float t  = __expf(-logit) * L1;
        out[e] = __fdividef(L2, L2 + t);
    }
}

// ---------------------------------------------------------------------------
// Inputs (metadata order): node_embed, edge_index, u1, u2, W1, b1, W2, b2
// ---------------------------------------------------------------------------
extern "C" void kernel_launch(void* const* d_in, const int* in_sizes, int n_in,
                              void* d_out, int out_size)
{
    const float* node_embed = (const float*)d_in[0];
    const void*  edge_index = d_in[1];
    const float* u1         = (const float*)d_in[2];
    const float* u2         = (const float*)d_in[3];
    const float* W1         = (const float*)d_in[4];
    const float* b1         = (const float*)d_in[5];
    const float* W2         = (const float*)d_in[6];
    const float* b2         = (const float*)d_in[7];
    float*       out        = (float*)d_out;

    const int num_nodes = in_sizes[0] / EMBED;
    const int num_edges = in_sizes[2];

    int gemm_blocks = (num_nodes + 31) / 32;
    pq_gemm_kernel<<<gemm_blocks, 256>>>(node_embed, W1, b1, (const int*)edge_index,
                                         num_nodes, num_edges);

    int edge_blocks = (num_edges + 31) / 32;
    edge_kernel<<<edge_blocks, 256>>>(edge_index, u1, u2, W2, b2, out, num_edges);
}

// round 11
// speedup vs baseline: 2.7834x; 1.6653x over previous
#include <cuda_runtime.h>
#include <cuda_fp16.h>
#include <cstdint>

#define EMBED      128
#define HID        64
#define MAX_NODES  50000
#define EPS_F      1e-10f

#define MTILE      64
#define SA_STRIDE  132     // A-fragment LDS conflict-free (132*g ≡ 4g mod 32)
#define SB_STRIDE  136     // B-fragment LDS conflict-free (136*t ≡ 8t mod 32)
#define SA_WORDS   (MTILE * SA_STRIDE)          // 8448
#define SB_WORDS   (128 * SB_STRIDE)            // 17408
#define SMEM_WORDS (SA_WORDS + SB_WORDS + HID)  // + b1
#define SMEM_BYTES (SMEM_WORDS * 4)

// PQ in fp16: PQh[n][0:64] = P = emb[n] @ W1[0:128];
//             PQh[n][64:128] = Q+b1 = emb[n] @ W1[128:256] + b1
__device__ __half g_PQh[(size_t)MAX_NODES * 128];
__device__ int g_idx_is64;

__device__ __forceinline__ uint32_t f2tf32(float f) {
    uint32_t r;
    asm("cvt.rna.tf32.f32 %0, %1;" : "=r"(r) : "f"(f));
    return r;
}

__device__ __forceinline__ void mma_tf32(float* d, const uint32_t* a, const uint32_t* b) {
    asm volatile(
        "mma.sync.aligned.m16n8k8.row.col.f32.tf32.tf32.f32 "
        "{%0,%1,%2,%3}, {%4,%5,%6,%7}, {%8,%9}, {%0,%1,%2,%3};"
        : "+f"(d[0]), "+f"(d[1]), "+f"(d[2]), "+f"(d[3])
        : "r"(a[0]), "r"(a[1]), "r"(a[2]), "r"(a[3]), "r"(b[0]), "r"(b[1]));
}

// ---------------------------------------------------------------------------
// Kernel 1 (tensor pipe via baseline mma.sync): PQ = emb @ W_eff (+ b1 fold).
// W_eff[k][j] = W1[k][j] (j<64) else W1[128+k][j-64]
// CTA: 64 node rows x 128 cols x K=128, 256 threads (8 warps, 2m x 4n grid,
// 32x32 warp tiles, 16 K-steps of m16n8k8 tf32).
// Block 0 / warp 7 also detects edge_index dtype.
// ---------------------------------------------------------------------------
__global__ void __launch_bounds__(256, 2) pq_tc_kernel(
    const float* __restrict__ emb,
    const float* __restrict__ W1,
    const float* __restrict__ b1,
    const int*   __restrict__ eidx32,
    int num_nodes, int num_edges)
{
    extern __shared__ uint32_t smem[];
    uint32_t* sA  = smem;                 // [64][132] tf32
    uint32_t* sB  = smem + SA_WORDS;      // [128][136] tf32 (k-major: [k][n])
    float*    sb1 = (float*)(smem + SA_WORDS + SB_WORDS);

    const int tid  = threadIdx.x;
    const int wid  = tid >> 5;
    const int lane = tid & 31;
    const int g    = lane >> 2;   // groupID
    const int t    = lane & 3;    // threadID_in_group
    const int row_base = blockIdx.x * MTILE;

    if (blockIdx.x == 0 && wid == 7) {
        int i = lane < num_edges ? lane : 0;
        int nz = (eidx32[2 * i + 1] != 0) ? 1 : 0;
        unsigned mask = __ballot_sync(0xffffffffu, nz);
        if (lane == 0) g_idx_is64 = (mask == 0u) ? 1 : 0;
    }

    if (tid < HID) sb1[tid] = b1[tid];

    // --- stage A: 64 rows x 128 cols of emb -> tf32, stride 132 ---
    #pragma unroll
    for (int i = 0; i < 8; i++) {
        int idx = i * 256 + tid;        // float4 index: 32 per row
        int row = idx >> 5;
        int c4  = idx & 31;
        int gr  = row_base + row;
        float4 v = make_float4(0.f, 0.f, 0.f, 0.f);
        if (gr < num_nodes)
            v = *reinterpret_cast<const float4*>(&emb[(size_t)gr * 128 + c4 * 4]);
        uint4 o = make_uint4(f2tf32(v.x), f2tf32(v.y), f2tf32(v.z), f2tf32(v.w));
        *reinterpret_cast<uint4*>(&sA[row * SA_STRIDE + c4 * 4]) = o;
    }

    // --- stage B: W1 (256x64) -> W_eff[k][n] tf32, stride 136 ---
    #pragma unroll
    for (int i = 0; i < 16; i++) {
        int f4i = i * 256 + tid;        // 4096 float4 total
        int r   = f4i >> 4;             // W1 row (0..255)
        int c   = (f4i & 15) * 4;       // W1 col (0..63, step 4)
        float4 v = *reinterpret_cast<const float4*>(&W1[(size_t)f4i * 4]);
        int k = (r < 128) ? r : (r - 128);
        int n = (r < 128) ? c : (c + 64);
        uint32_t* dst = &sB[k * SB_STRIDE + n];
        dst[0] = f2tf32(v.x); dst[1] = f2tf32(v.y);
        dst[2] = f2tf32(v.z); dst[3] = f2tf32(v.w);
    }
    __syncthreads();

    // --- warp MMA: warp (wm, wn), wm = wid & 1, wn = wid >> 1 ---
    const int wm = wid & 1;
    const int wn = wid >> 1;
    const int r0 = wm * 32;           // warp row offset in tile
    const int c0 = wn * 32;           // warp col offset

    float d[2][4][4];
    #pragma unroll
    for (int mi = 0; mi < 2; mi++)
        #pragma unroll
        for (int ni = 0; ni < 4; ni++)
            #pragma unroll
            for (int j = 0; j < 4; j++) d[mi][ni][j] = 0.f;

    #pragma unroll
    for (int ks = 0; ks < 16; ks++) {
        const int kb = ks * 8;
        uint32_t a[2][4], bf[4][2];
        #pragma unroll
        for (int mi = 0; mi < 2; mi++) {
            int rr = r0 + mi * 16;
            a[mi][0] = sA[(rr + g)     * SA_STRIDE + kb + t];
            a[mi][1] = sA[(rr + g + 8) * SA_STRIDE + kb + t];
            a[mi][2] = sA[(rr + g)     * SA_STRIDE + kb + t + 4];
            a[mi][3] = sA[(rr + g + 8) * SA_STRIDE + kb + t + 4];
        }
        #pragma unroll
        for (int ni = 0; ni < 4; ni++) {
            int cc = c0 + ni * 8;
            bf[ni][0] = sB[(kb + t)     * SB_STRIDE + cc + g];
            bf[ni][1] = sB[(kb + t + 4) * SB_STRIDE + cc + g];
        }
        #pragma unroll
        for (int mi = 0; mi < 2; mi++)
            #pragma unroll
            for (int ni = 0; ni < 4; ni++)
                mma_tf32(d[mi][ni], a[mi], bf[ni]);
    }

    // --- epilogue: fp16 store with b1 fold on cols >= 64 (wn >= 2) ---
    #pragma unroll
    for (int mi = 0; mi < 2; mi++) {
        const int ra = row_base + r0 + mi * 16 + g;
        const int rb = ra + 8;
        #pragma unroll
        for (int ni = 0; ni < 4; ni++) {
            const int c = c0 + ni * 8 + 2 * t;
            float b0 = 0.f, b1v = 0.f;
            if (wn >= 2) { b0 = sb1[c - 64]; b1v = sb1[c - 63]; }
            if (ra < num_nodes) {
                __half2 h = __floats2half2_rn(d[mi][ni][0] + b0, d[mi][ni][1] + b1v);
                *reinterpret_cast<__half2*>(&g_PQh[(size_t)ra * 128 + c]) = h;
            }
            if (rb < num_nodes) {
                __half2 h = __floats2half2_rn(d[mi][ni][2] + b0, d[mi][ni][3] + b1v);
                *reinterpret_cast<__half2*>(&g_PQh[(size_t)rb * 128 + c]) = h;
            }
        }
    }
}

// log(v) for v in (0,1]: MUFU __logf except near 1 (log1p polynomial fixes
// MUFU absolute-error blowup where -log(v) ~ (1-v)).
__device__ __forceinline__ float fast_log01(float v)
{
    float t = v - 1.0f;
    float p = 1.0f + t * (-0.5f + t * (0.33333333f + t * (-0.25f + t * 0.2f)));
    p *= t;
    float m = __logf(v);
    return (v > 0.9375f) ? p : m;
}

// ---------------------------------------------------------------------------
// Kernel 2: per-edge MLP tail + fused gumbel-sigmoid, fp16 data path.
// 8 lanes/edge; one LDG.128 per edge-half = one 128B line (L1 floor).
//   out = L2 / (L2 + exp(-logit)*L1),  L = -log(u)
// ---------------------------------------------------------------------------
__global__ void __launch_bounds__(256) edge_kernel(
    const void* __restrict__ eidx_raw,
    const float* __restrict__ u1,
    const float* __restrict__ u2,
    const float* __restrict__ W2,
    const float* __restrict__ b2,
    float* __restrict__ out,
    int num_edges)
{
    __shared__ __half2 sW2h[HID / 2];
    __shared__ float sb2;

    const int tid = threadIdx.x;
    if (tid < HID / 2)
        sW2h[tid] = __floats2half2_rn(W2[2 * tid], W2[2 * tid + 1]);
    if (tid == HID / 2) sb2 = b2[0];
    __syncthreads();

    const int g   = tid >> 3;
    const int gl  = tid & 7;
    const long long e_raw = (long long)blockIdx.x * 32 + g;
    const bool valid = (e_raw < num_edges);
    const long long e = valid ? e_raw : (long long)(num_edges - 1);

    int row, col;
    if (g_idx_is64) {
        const long long* eidx = (const long long*)eidx_raw;
        row = (int)eidx[e];
        col = (int)eidx[(long long)num_edges + e];
    } else {
        const int* eidx = (const int*)eidx_raw;
        row = eidx[e];
        col = eidx[(long long)num_edges + e];
    }

    const uint4 pv = *reinterpret_cast<const uint4*>(&g_PQh[(size_t)row * 128 + gl * 8]);
    const uint4 qv = *reinterpret_cast<const uint4*>(&g_PQh[(size_t)col * 128 + 64 + gl * 8]);
    const uint4 wv = *reinterpret_cast<const uint4*>(&sW2h[gl * 4]);

    const __half2* p2 = reinterpret_cast<const __half2*>(&pv);
    const __half2* q2 = reinterpret_cast<const __half2*>(&qv);
    const __half2* w2 = reinterpret_cast<const __half2*>(&wv);

    const __half2 z2 = __float2half2_rn(0.f);
    __half2 acc2 = z2;
    #pragma unroll
    for (int i = 0; i < 4; i++) {
        __half2 h = __hmax2(__hadd2(p2[i], q2[i]), z2);
        acc2 = __hfma2(h, w2[i], acc2);
    }
    float2 f = __half22float2(acc2);
    float partial = f.x + f.y;
    partial += __shfl_xor_sync(0xffffffffu, partial, 1);
    partial += __shfl_xor_sync(0xffffffffu, partial, 2);
    partial += __shfl_xor_sync(0xffffffffu, partial, 4);

    if (gl == 0 && valid) {
        float logit = partial + sb2;
        float v1 = fminf(fmaxf(u1[e], EPS_F), 1.0f - EPS_F);
        float v2 = fminf(fmaxf(u2[e], EPS_F), 1.0f - EPS_F);
        float L1 = -fast_log01(v1);
        float L2 = -fast_log01(v2);
        float t  = __expf(-logit) * L1;
        out[e] = __fdividef(L2, L2 + t);
    }
}

// ---------------------------------------------------------------------------
// Inputs (metadata order): node_embed, edge_index, u1, u2, W1, b1, W2, b2
// ---------------------------------------------------------------------------
extern "C" void kernel_launch(void* const* d_in, const int* in_sizes, int n_in,
                              void* d_out, int out_size)
{
    const float* node_embed = (const float*)d_in[0];
    const void*  edge_index = d_in[1];
    const float* u1         = (const float*)d_in[2];
    const float* u2         = (const float*)d_in[3];
    const float* W1         = (const float*)d_in[4];
    const float* b1         = (const float*)d_in[5];
    const float* W2         = (const float*)d_in[6];
    const float* b2         = (const float*)d_in[7];
    float*       out        = (float*)d_out;

    const int num_nodes = in_sizes[0] / EMBED;
    const int num_edges = in_sizes[2];

    static bool attr_set = false;
    if (!attr_set) {
        cudaFuncSetAttribute(pq_tc_kernel,
                             cudaFuncAttributeMaxDynamicSharedMemorySize, SMEM_BYTES);
        attr_set = true;
    }

    int gemm_blocks = (num_nodes + MTILE - 1) / MTILE;
    pq_tc_kernel<<<gemm_blocks, 256, SMEM_BYTES>>>(node_embed, W1, b1,
                                                   (const int*)edge_index,
                                                   num_nodes, num_edges);

    int edge_blocks = (num_edges + 31) / 32;
    edge_kernel<<<edge_blocks, 256>>>(edge_index, u1, u2, W2, b2, out, num_edges);
}

// round 12
// speedup vs baseline: 3.3612x; 1.2076x over previous
#include <cuda_runtime.h>
#include <cuda_fp16.h>
#include <cstdint>

#define EMBED      128
#define HID        64
#define MAX_NODES  50000
#define EPS_F      1e-10f

#define MTILE      64
#define SA_STRIDE  132     // A-fragment LDS conflict-free
#define SB_STRIDE  136     // B-fragment LDS conflict-free
#define SA_WORDS   (MTILE * SA_STRIDE)
#define SB_WORDS   (128 * SB_STRIDE)
#define SMEM_WORDS (SA_WORDS + SB_WORDS + HID)
#define SMEM_BYTES (SMEM_WORDS * 4)

// PQ in fp16: PQh[n][0:64] = P = emb[n] @ W1[0:128];
//             PQh[n][64:128] = Q+b1 = emb[n] @ W1[128:256] + b1
__device__ __half g_PQh[(size_t)MAX_NODES * 128];
__device__ int g_idx_is64;

__device__ __forceinline__ uint32_t f2tf32(float f) {
    uint32_t r;
    asm("cvt.rna.tf32.f32 %0, %1;" : "=r"(r) : "f"(f));
    return r;
}

__device__ __forceinline__ void mma_tf32(float* d, const uint32_t* a, const uint32_t* b) {
    asm volatile(
        "mma.sync.aligned.m16n8k8.row.col.f32.tf32.tf32.f32 "
        "{%0,%1,%2,%3}, {%4,%5,%6,%7}, {%8,%9}, {%0,%1,%2,%3};"
        : "+f"(d[0]), "+f"(d[1]), "+f"(d[2]), "+f"(d[3])
        : "r"(a[0]), "r"(a[1]), "r"(a[2]), "r"(a[3]), "r"(b[0]), "r"(b[1]));
}

// ---------------------------------------------------------------------------
// Kernel 1 (tensor pipe, proven R11): PQ = emb @ W_eff (+ b1 fold), tf32 MMA.
// CTA: 64 rows x 128 cols x K=128, 8 warps (2m x 4n), 32x32 warp tiles.
// ---------------------------------------------------------------------------
__global__ void __launch_bounds__(256, 2) pq_tc_kernel(
    const float* __restrict__ emb,
    const float* __restrict__ W1,
    const float* __restrict__ b1,
    const int*   __restrict__ eidx32,
    int num_nodes, int num_edges)
{
    extern __shared__ uint32_t smem[];
    uint32_t* sA  = smem;
    uint32_t* sB  = smem + SA_WORDS;
    float*    sb1 = (float*)(smem + SA_WORDS + SB_WORDS);

    const int tid  = threadIdx.x;
    const int wid  = tid >> 5;
    const int lane = tid & 31;
    const int g    = lane >> 2;
    const int t    = lane & 3;
    const int row_base = blockIdx.x * MTILE;

    if (blockIdx.x == 0 && wid == 7) {
        int i = lane < num_edges ? lane : 0;
        int nz = (eidx32[2 * i + 1] != 0) ? 1 : 0;
        unsigned mask = __ballot_sync(0xffffffffu, nz);
        if (lane == 0) g_idx_is64 = (mask == 0u) ? 1 : 0;
    }

    if (tid < HID) sb1[tid] = b1[tid];

    #pragma unroll
    for (int i = 0; i < 8; i++) {
        int idx = i * 256 + tid;
        int row = idx >> 5;
        int c4  = idx & 31;
        int gr  = row_base + row;
        float4 v = make_float4(0.f, 0.f, 0.f, 0.f);
        if (gr < num_nodes)
            v = *reinterpret_cast<const float4*>(&emb[(size_t)gr * 128 + c4 * 4]);
        uint4 o = make_uint4(f2tf32(v.x), f2tf32(v.y), f2tf32(v.z), f2tf32(v.w));
        *reinterpret_cast<uint4*>(&sA[row * SA_STRIDE + c4 * 4]) = o;
    }

    #pragma unroll
    for (int i = 0; i < 16; i++) {
        int f4i = i * 256 + tid;
        int r   = f4i >> 4;
        int c   = (f4i & 15) * 4;
        float4 v = *reinterpret_cast<const float4*>(&W1[(size_t)f4i * 4]);
        int k = (r < 128) ? r : (r - 128);
        int n = (r < 128) ? c : (c + 64);
        uint32_t* dst = &sB[k * SB_STRIDE + n];
        dst[0] = f2tf32(v.x); dst[1] = f2tf32(v.y);
        dst[2] = f2tf32(v.z); dst[3] = f2tf32(v.w);
    }
    __syncthreads();

    const int wm = wid & 1;
    const int wn = wid >> 1;
    const int r0 = wm * 32;
    const int c0 = wn * 32;

    float d[2][4][4];
    #pragma unroll
    for (int mi = 0; mi < 2; mi++)
        #pragma unroll
        for (int ni = 0; ni < 4; ni++)
            #pragma unroll
            for (int j = 0; j < 4; j++) d[mi][ni][j] = 0.f;

    #pragma unroll
    for (int ks = 0; ks < 16; ks++) {
        const int kb = ks * 8;
        uint32_t a[2][4], bf[4][2];
        #pragma unroll
        for (int mi = 0; mi < 2; mi++) {
            int rr = r0 + mi * 16;
            a[mi][0] = sA[(rr + g)     * SA_STRIDE + kb + t];
            a[mi][1] = sA[(rr + g + 8) * SA_STRIDE + kb + t];
            a[mi][2] = sA[(rr + g)     * SA_STRIDE + kb + t + 4];
            a[mi][3] = sA[(rr + g + 8) * SA_STRIDE + kb + t + 4];
        }
        #pragma unroll
        for (int ni = 0; ni < 4; ni++) {
            int cc = c0 + ni * 8;
            bf[ni][0] = sB[(kb + t)     * SB_STRIDE + cc + g];
            bf[ni][1] = sB[(kb + t + 4) * SB_STRIDE + cc + g];
        }
        #pragma unroll
        for (int mi = 0; mi < 2; mi++)
            #pragma unroll
            for (int ni = 0; ni < 4; ni++)
                mma_tf32(d[mi][ni], a[mi], bf[ni]);
    }

    #pragma unroll
    for (int mi = 0; mi < 2; mi++) {
        const int ra = row_base + r0 + mi * 16 + g;
        const int rb = ra + 8;
        #pragma unroll
        for (int ni = 0; ni < 4; ni++) {
            const int c = c0 + ni * 8 + 2 * t;
            float b0 = 0.f, b1v = 0.f;
            if (wn >= 2) { b0 = sb1[c - 64]; b1v = sb1[c - 63]; }
            if (ra < num_nodes) {
                __half2 h = __floats2half2_rn(d[mi][ni][0] + b0, d[mi][ni][1] + b1v);
                *reinterpret_cast<__half2*>(&g_PQh[(size_t)ra * 128 + c]) = h;
            }
            if (rb < num_nodes) {
                __half2 h = __floats2half2_rn(d[mi][ni][2] + b0, d[mi][ni][3] + b1v);
                *reinterpret_cast<__half2*>(&g_PQh[(size_t)rb * 128 + c]) = h;
            }
        }
    }
}

// log(v) for v in (0,1]: MUFU __logf except near 1 (log1p polynomial fixes
// MUFU absolute-error blowup where -log(v) ~ (1-v)).
__device__ __forceinline__ float fast_log01(float v)
{
    float t = v - 1.0f;
    float p = 1.0f + t * (-0.5f + t * (0.33333333f + t * (-0.25f + t * 0.2f)));
    p *= t;
    float m = __logf(v);
    return (v > 0.9375f) ? p : m;
}

// 8-lane partial dot: relu(p+q) . w in half2
__device__ __forceinline__ float dot8h(const uint4& pv, const uint4& qv, const uint4& wv)
{
    const __half2* p2 = reinterpret_cast<const __half2*>(&pv);
    const __half2* q2 = reinterpret_cast<const __half2*>(&qv);
    const __half2* w2 = reinterpret_cast<const __half2*>(&wv);
    const __half2 z2 = __float2half2_rn(0.f);
    __half2 acc2 = z2;
    #pragma unroll
    for (int i = 0; i < 4; i++) {
        __half2 h = __hmax2(__hadd2(p2[i], q2[i]), z2);
        acc2 = __hfma2(h, w2[i], acc2);
    }
    float2 f = __half22float2(acc2);
    return f.x + f.y;
}

// ---------------------------------------------------------------------------
// Kernel 2: per-edge MLP tail + fused gumbel-sigmoid, two-phase.
// Phase 1: 8 lanes/edge, 2 edges/group (ILP); logits parked in smem.
// Phase 2: threads 0..63 run Gumbel tails densely (coalesced u1/u2/out).
//   out = L2 / (L2 + exp(-logit)*L1),  L = -log(u)
// ---------------------------------------------------------------------------
__global__ void __launch_bounds__(256) edge_kernel(
    const void* __restrict__ eidx_raw,
    const float* __restrict__ u1,
    const float* __restrict__ u2,
    const float* __restrict__ W2,
    const float* __restrict__ b2,
    float* __restrict__ out,
    int num_edges)
{
    __shared__ __half2 sW2h[HID / 2];
    __shared__ float sb2;
    __shared__ float slog[64];

    const int tid = threadIdx.x;
    if (tid < HID / 2)
        sW2h[tid] = __floats2half2_rn(W2[2 * tid], W2[2 * tid + 1]);
    if (tid == HID / 2) sb2 = b2[0];
    __syncthreads();

    const int g   = tid >> 3;    // group 0..31
    const int gl  = tid & 7;     // lane within group
    const int base = blockIdx.x * 64;

    // Two edges per group; clamp for safe loads (store guarded in phase 2).
    const long long eA = min((long long)(base + g),      (long long)num_edges - 1);
    const long long eB = min((long long)(base + 32 + g), (long long)num_edges - 1);

    int rowA, colA, rowB, colB;
    if (g_idx_is64) {
        const long long* eidx = (const long long*)eidx_raw;
        rowA = (int)eidx[eA];
        colA = (int)eidx[(long long)num_edges + eA];
        rowB = (int)eidx[eB];
        colB = (int)eidx[(long long)num_edges + eB];
    } else {
        const int* eidx = (const int*)eidx_raw;
        rowA = eidx[eA];
        colA = eidx[(long long)num_edges + eA];
        rowB = eidx[eB];
        colB = eidx[(long long)num_edges + eB];
    }

    // Issue all 4 gathers before any math (MLP=4 per lane).
    const uint4 pvA = *reinterpret_cast<const uint4*>(&g_PQh[(size_t)rowA * 128 + gl * 8]);
    const uint4 qvA = *reinterpret_cast<const uint4*>(&g_PQh[(size_t)colA * 128 + 64 + gl * 8]);
    const uint4 pvB = *reinterpret_cast<const uint4*>(&g_PQh[(size_t)rowB * 128 + gl * 8]);
    const uint4 qvB = *reinterpret_cast<const uint4*>(&g_PQh[(size_t)colB * 128 + 64 + gl * 8]);
    const uint4 wv  = *reinterpret_cast<const uint4*>(&sW2h[gl * 4]);

    float pA = dot8h(pvA, qvA, wv);
    float pB = dot8h(pvB, qvB, wv);

    pA += __shfl_xor_sync(0xffffffffu, pA, 1);
    pB += __shfl_xor_sync(0xffffffffu, pB, 1);
    pA += __shfl_xor_sync(0xffffffffu, pA, 2);
    pB += __shfl_xor_sync(0xffffffffu, pB, 2);
    pA += __shfl_xor_sync(0xffffffffu, pA, 4);
    pB += __shfl_xor_sync(0xffffffffu, pB, 4);

    if (gl == 0) {
        slog[g]      = pA;
        slog[32 + g] = pB;
    }
    __syncthreads();

    // Phase 2: dense tails, coalesced u1/u2/out.
    if (tid < 64) {
        const long long e = (long long)base + tid;
        if (e < num_edges) {
            float logit = slog[tid] + sb2;
            float v1 = fminf(fmaxf(u1[e], EPS_F), 1.0f - EPS_F);
            float v2 = fminf(fmaxf(u2[e], EPS_F), 1.0f - EPS_F);
            float L1 = -fast_log01(v1);
            float L2 = -fast_log01(v2);
            float t  = __expf(-logit) * L1;
            out[e] = __fdividef(L2, L2 + t);
        }
    }
}

// ---------------------------------------------------------------------------
// Inputs (metadata order): node_embed, edge_index, u1, u2, W1, b1, W2, b2
// ---------------------------------------------------------------------------
extern "C" void kernel_launch(void* const* d_in, const int* in_sizes, int n_in,
                              void* d_out, int out_size)
{
    const float* node_embed = (const float*)d_in[0];
    const void*  edge_index = d_in[1];
    const float* u1         = (const float*)d_in[2];
    const float* u2         = (const float*)d_in[3];
    const float* W1         = (const float*)d_in[4];
    const float* b1         = (const float*)d_in[5];
    const float* W2         = (const float*)d_in[6];
    const float* b2         = (const float*)d_in[7];
    float*       out        = (float*)d_out;

    const int num_nodes = in_sizes[0] / EMBED;
    const int num_edges = in_sizes[2];

    static bool attr_set = false;
    if (!attr_set) {
        cudaFuncSetAttribute(pq_tc_kernel,
                             cudaFuncAttributeMaxDynamicSharedMemorySize, SMEM_BYTES);
        attr_set = true;
    }

    int gemm_blocks = (num_nodes + MTILE - 1) / MTILE;
    pq_tc_kernel<<<gemm_blocks, 256, SMEM_BYTES>>>(node_embed, W1, b1,
                                                   (const int*)edge_index,
                                                   num_nodes, num_edges);

    int edge_blocks = (num_edges + 63) / 64;
    edge_kernel<<<edge_blocks, 256>>>(edge_index, u1, u2, W2, b2, out, num_edges);
}

// round 16
// speedup vs baseline: 3.4575x; 1.0286x over previous
#include <cuda_runtime.h>
#include <cuda_fp16.h>
#include <cstdint>

#define EMBED      128
#define HID        64
#define MAX_NODES  50000
#define EPS_F      1e-10f

#define MTILE      64
#define SA_STRIDE  132     // A-fragment LDS conflict-free
#define SB_STRIDE  136     // B-fragment LDS conflict-free
#define SA_WORDS   (MTILE * SA_STRIDE)
#define SB_WORDS   (128 * SB_STRIDE)
#define SMEM_WORDS (SA_WORDS + SB_WORDS + HID)
#define SMEM_BYTES (SMEM_WORDS * 4)

// PQ in fp16: PQh[n][0:64] = P = emb[n] @ W1[0:128];
//             PQh[n][64:128] = Q+b1 = emb[n] @ W1[128:256] + b1
__device__ __half g_PQh[(size_t)MAX_NODES * 128];
__device__ int g_idx_is64;

// Raw f32 bits fed to the tf32 MMA: the tensor pipe reads only the top 19
// bits (RZ truncation instead of RNA rounding) — saves all cvt issues.
__device__ __forceinline__ uint32_t f2tf32(float f) { return __float_as_uint(f); }

__device__ __forceinline__ void mma_tf32(float* d, const uint32_t* a, const uint32_t* b) {
    asm volatile(
        "mma.sync.aligned.m16n8k8.row.col.f32.tf32.tf32.f32 "
        "{%0,%1,%2,%3}, {%4,%5,%6,%7}, {%8,%9}, {%0,%1,%2,%3};"
        : "+f"(d[0]), "+f"(d[1]), "+f"(d[2]), "+f"(d[3])
        : "r"(a[0]), "r"(a[1]), "r"(a[2]), "r"(a[3]), "r"(b[0]), "r"(b[1]));
}

// ---------------------------------------------------------------------------
// Kernel 1 (tensor pipe): PQ = emb @ W_eff (+ b1 fold), tf32 MMA.
// CTA: 64 rows x 128 cols x K=128, 8 warps (2m x 4n), 32x32 warp tiles.
// ---------------------------------------------------------------------------
__global__ void __launch_bounds__(256, 2) pq_tc_kernel(
    const float* __restrict__ emb,
    const float* __restrict__ W1,
    const float* __restrict__ b1,
    const int*   __restrict__ eidx32,
    int num_nodes, int num_edges)
{
    extern __shared__ uint32_t smem[];
    uint32_t* sA  = smem;
    uint32_t* sB  = smem + SA_WORDS;
    float*    sb1 = (float*)(smem + SA_WORDS + SB_WORDS);

    const int tid  = threadIdx.x;
    const int wid  = tid >> 5;
    const int lane = tid & 31;
    const int g    = lane >> 2;
    const int t    = lane & 3;
    const int row_base = blockIdx.x * MTILE;

    if (blockIdx.x == 0 && wid == 7) {
        int i = lane < num_edges ? lane : 0;
        int nz = (eidx32[2 * i + 1] != 0) ? 1 : 0;
        unsigned mask = __ballot_sync(0xffffffffu, nz);
        if (lane == 0) g_idx_is64 = (mask == 0u) ? 1 : 0;
    }

    if (tid < HID) sb1[tid] = b1[tid];

    #pragma unroll
    for (int i = 0; i < 8; i++) {
        int idx = i * 256 + tid;
        int row = idx >> 5;
        int c4  = idx & 31;
        int gr  = row_base + row;
        float4 v = make_float4(0.f, 0.f, 0.f, 0.f);
        if (gr < num_nodes)
            v = *reinterpret_cast<const float4*>(&emb[(size_t)gr * 128 + c4 * 4]);
        uint4 o = make_uint4(f2tf32(v.x), f2tf32(v.y), f2tf32(v.z), f2tf32(v.w));
        *reinterpret_cast<uint4*>(&sA[row * SA_STRIDE + c4 * 4]) = o;
    }

    #pragma unroll
    for (int i = 0; i < 16; i++) {
        int f4i = i * 256 + tid;
        int r   = f4i >> 4;
        int c   = (f4i & 15) * 4;
        float4 v = *reinterpret_cast<const float4*>(&W1[(size_t)f4i * 4]);
        int k = (r < 128) ? r : (r - 128);
        int n = (r < 128) ? c : (c + 64);
        uint32_t* dst = &sB[k * SB_STRIDE + n];
        dst[0] = f2tf32(v.x); dst[1] = f2tf32(v.y);
        dst[2] = f2tf32(v.z); dst[3] = f2tf32(v.w);
    }
    __syncthreads();

    const int wm = wid & 1;
    const int wn = wid >> 1;
    const int r0 = wm * 32;
    const int c0 = wn * 32;

    float d[2][4][4];
    #pragma unroll
    for (int mi = 0; mi < 2; mi++)
        #pragma unroll
        for (int ni = 0; ni < 4; ni++)
            #pragma unroll
            for (int j = 0; j < 4; j++) d[mi][ni][j] = 0.f;

    #pragma unroll
    for (int ks = 0; ks < 16; ks++) {
        const int kb = ks * 8;
        uint32_t a[2][4], bf[4][2];
        #pragma unroll
        for (int mi = 0; mi < 2; mi++) {
            int rr = r0 + mi * 16;
            a[mi][0] = sA[(rr + g)     * SA_STRIDE + kb + t];
            a[mi][1] = sA[(rr + g + 8) * SA_STRIDE + kb + t];
            a[mi][2] = sA[(rr + g)     * SA_STRIDE + kb + t + 4];
            a[mi][3] = sA[(rr + g + 8) * SA_STRIDE + kb + t + 4];
        }
        #pragma unroll
        for (int ni = 0; ni < 4; ni++) {
            int cc = c0 + ni * 8;
            bf[ni][0] = sB[(kb + t)     * SB_STRIDE + cc + g];
            bf[ni][1] = sB[(kb + t + 4) * SB_STRIDE + cc + g];
        }
        #pragma unroll
        for (int mi = 0; mi < 2; mi++)
            #pragma unroll
            for (int ni = 0; ni < 4; ni++)
                mma_tf32(d[mi][ni], a[mi], bf[ni]);
    }

    #pragma unroll
    for (int mi = 0; mi < 2; mi++) {
        const int ra = row_base + r0 + mi * 16 + g;
        const int rb = ra + 8;
        #pragma unroll
        for (int ni = 0; ni < 4; ni++) {
            const int c = c0 + ni * 8 + 2 * t;
            float b0 = 0.f, b1v = 0.f;
            if (wn >= 2) { b0 = sb1[c - 64]; b1v = sb1[c - 63]; }
            if (ra < num_nodes) {
                __half2 h = __floats2half2_rn(d[mi][ni][0] + b0, d[mi][ni][1] + b1v);
                *reinterpret_cast<__half2*>(&g_PQh[(size_t)ra * 128 + c]) = h;
            }
            if (rb < num_nodes) {
                __half2 h = __floats2half2_rn(d[mi][ni][2] + b0, d[mi][ni][3] + b1v);
                *reinterpret_cast<__half2*>(&g_PQh[(size_t)rb * 128 + c]) = h;
            }
        }
    }
}

// log(v) for v in (0,1]: MUFU __logf except near 1 (log1p polynomial fixes
// MUFU absolute-error blowup where -log(v) ~ (1-v)).
__device__ __forceinline__ float fast_log01(float v)
{
    float t = v - 1.0f;
    float p = 1.0f + t * (-0.5f + t * (0.33333333f + t * (-0.25f + t * 0.2f)));
    p *= t;
    float m = __logf(v);
    return (v > 0.9375f) ? p : m;
}

// 8-lane partial dot: relu(p+q) . w in half2
__device__ __forceinline__ float dot8h(const uint4& pv, const uint4& qv, const uint4& wv)
{
    const __half2* p2 = reinterpret_cast<const __half2*>(&pv);
    const __half2* q2 = reinterpret_cast<const __half2*>(&qv);
    const __half2* w2 = reinterpret_cast<const __half2*>(&wv);
    const __half2 z2 = __float2half2_rn(0.f);
    __half2 acc2 = z2;
    #pragma unroll
    for (int i = 0; i < 4; i++) {
        __half2 h = __hmax2(__hadd2(p2[i], q2[i]), z2);
        acc2 = __hfma2(h, w2[i], acc2);
    }
    float2 f = __half22float2(acc2);
    return f.x + f.y;
}

// ---------------------------------------------------------------------------
// Kernel 2: per-edge MLP tail + fused gumbel-sigmoid, three-phase.
// Phase 0: threads 0..127 stage edge indices coalesced into smem.
// Phase 1: 8 lanes/edge, 4 edges/group (8 in-flight gathers per lane);
//          logits shuffled down and parked in smem.
// Phase 2: threads 0..127 run Gumbel tails densely (coalesced u1/u2/out).
//   out = L2 / (L2 + exp(-logit)*L1),  L = -log(u)
// ---------------------------------------------------------------------------
__global__ void __launch_bounds__(256) edge_kernel(
    const void* __restrict__ eidx_raw,
    const float* __restrict__ u1,
    const float* __restrict__ u2,
    const float* __restrict__ W2,
    const float* __restrict__ b2,
    float* __restrict__ out,
    int num_edges)
{
    __shared__ __half2 sW2h[HID / 2];
    __shared__ float sb2;
    __shared__ int2 sIdx[128];
    __shared__ float slog[128];

    const int tid  = threadIdx.x;
    const int base = blockIdx.x * 128;

    if (tid < HID / 2)
        sW2h[tid] = __floats2half2_rn(W2[2 * tid], W2[2 * tid + 1]);
    if (tid == HID / 2) sb2 = b2[0];

    // Phase 0: coalesced index staging (clamped; stores guarded in phase 2).
    if (tid < 128) {
        long long e = (long long)(base + tid);
        if (e >= num_edges) e = num_edges - 1;
        int row, col;
        if (g_idx_is64) {
            const long long* eidx = (const long long*)eidx_raw;
            row = (int)eidx[e];
            col = (int)eidx[(long long)num_edges + e];
        } else {
            const int* eidx = (const int*)eidx_raw;
            row = eidx[e];
            col = eidx[(long long)num_edges + e];
        }
        sIdx[tid] = make_int2(row, col);
    }
    __syncthreads();

    // Phase 1: 32 groups x 4 edges.
    const int g  = tid >> 3;
    const int gl = tid & 7;

    const uint4 wv = *reinterpret_cast<const uint4*>(&sW2h[gl * 4]);

    int2 idx[4];
    #pragma unroll
    for (int j = 0; j < 4; j++) idx[j] = sIdx[j * 32 + g];

    uint4 pv[4], qv[4];
    #pragma unroll
    for (int j = 0; j < 4; j++) {
        pv[j] = *reinterpret_cast<const uint4*>(&g_PQh[(size_t)idx[j].x * 128 + gl * 8]);
        qv[j] = *reinterpret_cast<const uint4*>(&g_PQh[(size_t)idx[j].y * 128 + 64 + gl * 8]);
    }

    float p[4];
    #pragma unroll
    for (int j = 0; j < 4; j++) p[j] = dot8h(pv[j], qv[j], wv);

    #pragma unroll
    for (int j = 0; j < 4; j++) p[j] += __shfl_xor_sync(0xffffffffu, p[j], 1);
    #pragma unroll
    for (int j = 0; j < 4; j++) p[j] += __shfl_xor_sync(0xffffffffu, p[j], 2);
    #pragma unroll
    for (int j = 0; j < 4; j++) p[j] += __shfl_xor_sync(0xffffffffu, p[j], 4);

    if (gl == 0) {
        #pragma unroll
        for (int j = 0; j < 4; j++) slog[j * 32 + g] = p[j];
    }
    __syncthreads();

    // Phase 2: dense tails.
    if (tid < 128) {
        const long long e = (long long)base + tid;
        if (e < num_edges) {
            float logit = slog[tid] + sb2;
            float v1 = fminf(fmaxf(u1[e], EPS_F), 1.0f - EPS_F);
            float v2 = fminf(fmaxf(u2[e], EPS_F), 1.0f - EPS_F);
            float L1 = -fast_log01(v1);
            float L2 = -fast_log01(v2);
            float t  = __expf(-logit) * L1;
            out[e] = __fdividef(L2, L2 + t);
        }
    }
}

// ---------------------------------------------------------------------------
// Inputs (metadata order): node_embed, edge_index, u1, u2, W1, b1, W2, b2
// ---------------------------------------------------------------------------
extern "C" void kernel_launch(void* const* d_in, const int* in_sizes, int n_in,
                              void* d_out, int out_size)
{
    const float* node_embed = (const float*)d_in[0];
    const void*  edge_index = d_in[1];
    const float* u1         = (const float*)d_in[2];
    const float* u2         = (const float*)d_in[3];
    const float* W1         = (const float*)d_in[4];
    const float* b1         = (const float*)d_in[5];
    const float* W2         = (const float*)d_in[6];
    const float* b2         = (const float*)d_in[7];
    float*       out        = (float*)d_out;

    const int num_nodes = in_sizes[0] / EMBED;
    const int num_edges = in_sizes[2];

    static bool attr_set = false;
    if (!attr_set) {
        cudaFuncSetAttribute(pq_tc_kernel,
                             cudaFuncAttributeMaxDynamicSharedMemorySize, SMEM_BYTES);
        attr_set = true;
    }

    int gemm_blocks = (num_nodes + MTILE - 1) / MTILE;
    pq_tc_kernel<<<gemm_blocks, 256, SMEM_BYTES>>>(node_embed, W1, b1,
                                                   (const int*)edge_index,
                                                   num_nodes, num_edges);

    int edge_blocks = (num_edges + 127) / 128;
    edge_kernel<<<edge_blocks, 256>>>(edge_index, u1, u2, W2, b2, out, num_edges);
}

// round 17
// speedup vs baseline: 3.6111x; 1.0444x over previous
#include <cuda_runtime.h>
#include <cuda_fp16.h>
#include <cstdint>

#define EMBED      128
#define HID        64
#define MAX_NODES  50000
#define EPS_F      1e-10f

#define MTILE      128
#define NTHREADS   512
#define SA_STRIDE  132     // A-fragment LDS conflict-free
#define SB_STRIDE  136     // B-fragment LDS conflict-free
#define SA_WORDS   (MTILE * SA_STRIDE)          // 16896
#define SB_WORDS   (128 * SB_STRIDE)            // 17408
#define SMEM_WORDS (SA_WORDS + SB_WORDS + HID)
#define SMEM_BYTES (SMEM_WORDS * 4)             // ~137.5 KB

// PQ in fp16: PQh[n][0:64] = P = emb[n] @ W1[0:128];
//             PQh[n][64:128] = Q+b1 = emb[n] @ W1[128:256] + b1
__device__ __half g_PQh[(size_t)MAX_NODES * 128];
__device__ int g_idx_is64;

// Raw f32 bits fed to the tf32 MMA (HW truncates to top 19 bits).
__device__ __forceinline__ uint32_t f2tf32(float f) { return __float_as_uint(f); }

__device__ __forceinline__ void mma_tf32(float* d, const uint32_t* a, const uint32_t* b) {
    asm volatile(
        "mma.sync.aligned.m16n8k8.row.col.f32.tf32.tf32.f32 "
        "{%0,%1,%2,%3}, {%4,%5,%6,%7}, {%8,%9}, {%0,%1,%2,%3};"
        : "+f"(d[0]), "+f"(d[1]), "+f"(d[2]), "+f"(d[3])
        : "r"(a[0]), "r"(a[1]), "r"(a[2]), "r"(a[3]), "r"(b[0]), "r"(b[1]));
}

// ---------------------------------------------------------------------------
// Kernel 1 (tensor pipe): PQ = emb @ W_eff (+ b1 fold), tf32 MMA.
// CTA: 128 rows x 128 cols x K=128, 512 threads (16 warps, 4m x 4n grid,
// 32x32 warp tiles). Halves W1 re-staging L2 traffic vs MTILE=64.
// ---------------------------------------------------------------------------
__global__ void __launch_bounds__(NTHREADS, 1) pq_tc_kernel(
    const float* __restrict__ emb,
    const float* __restrict__ W1,
    const float* __restrict__ b1,
    const int*   __restrict__ eidx32,
    int num_nodes, int num_edges)
{
    extern __shared__ uint32_t smem[];
    uint32_t* sA  = smem;
    uint32_t* sB  = smem + SA_WORDS;
    float*    sb1 = (float*)(smem + SA_WORDS + SB_WORDS);

    const int tid  = threadIdx.x;
    const int wid  = tid >> 5;
    const int lane = tid & 31;
    const int g    = lane >> 2;
    const int t    = lane & 3;
    const int row_base = blockIdx.x * MTILE;

    // Fused edge_index dtype detect (block 0, warp 15): int64 indices < 2^31
    // have all-zero odd 32-bit words; 32 random int32 all-zero is impossible.
    if (blockIdx.x == 0 && wid == 15) {
        int i = lane < num_edges ? lane : 0;
        int nz = (eidx32[2 * i + 1] != 0) ? 1 : 0;
        unsigned mask = __ballot_sync(0xffffffffu, nz);
        if (lane == 0) g_idx_is64 = (mask == 0u) ? 1 : 0;
    }

    if (tid < HID) sb1[tid] = b1[tid];

    // --- stage A: 128 rows x 128 cols of emb (4096 float4, 8/thread) ---
    #pragma unroll
    for (int i = 0; i < 8; i++) {
        int idx = i * NTHREADS + tid;
        int row = idx >> 5;
        int c4  = idx & 31;
        int gr  = row_base + row;
        float4 v = make_float4(0.f, 0.f, 0.f, 0.f);
        if (gr < num_nodes)
            v = *reinterpret_cast<const float4*>(&emb[(size_t)gr * 128 + c4 * 4]);
        uint4 o = make_uint4(f2tf32(v.x), f2tf32(v.y), f2tf32(v.z), f2tf32(v.w));
        *reinterpret_cast<uint4*>(&sA[row * SA_STRIDE + c4 * 4]) = o;
    }

    // --- stage B: W1 (256x64) -> W_eff[k][n] (4096 float4, 8/thread) ---
    #pragma unroll
    for (int i = 0; i < 8; i++) {
        int f4i = i * NTHREADS + tid;
        int r   = f4i >> 4;
        int c   = (f4i & 15) * 4;
        float4 v = *reinterpret_cast<const float4*>(&W1[(size_t)f4i * 4]);
        int k = (r < 128) ? r : (r - 128);
        int n = (r < 128) ? c : (c + 64);
        uint4 o = make_uint4(f2tf32(v.x), f2tf32(v.y), f2tf32(v.z), f2tf32(v.w));
        *reinterpret_cast<uint4*>(&sB[k * SB_STRIDE + n]) = o;
    }
    __syncthreads();

    // --- warp MMA: 4m x 4n grid of 32x32 warp tiles ---
    const int wm = wid & 3;
    const int wn = wid >> 2;
    const int r0 = wm * 32;
    const int c0 = wn * 32;

    float d[2][4][4];
    #pragma unroll
    for (int mi = 0; mi < 2; mi++)
        #pragma unroll
        for (int ni = 0; ni < 4; ni++)
            #pragma unroll
            for (int j = 0; j < 4; j++) d[mi][ni][j] = 0.f;

    #pragma unroll
    for (int ks = 0; ks < 16; ks++) {
        const int kb = ks * 8;
        uint32_t a[2][4], bf[4][2];
        #pragma unroll
        for (int mi = 0; mi < 2; mi++) {
            int rr = r0 + mi * 16;
            a[mi][0] = sA[(rr + g)     * SA_STRIDE + kb + t];
            a[mi][1] = sA[(rr + g + 8) * SA_STRIDE + kb + t];
            a[mi][2] = sA[(rr + g)     * SA_STRIDE + kb + t + 4];
            a[mi][3] = sA[(rr + g + 8) * SA_STRIDE + kb + t + 4];
        }
        #pragma unroll
        for (int ni = 0; ni < 4; ni++) {
            int cc = c0 + ni * 8;
            bf[ni][0] = sB[(kb + t)     * SB_STRIDE + cc + g];
            bf[ni][1] = sB[(kb + t + 4) * SB_STRIDE + cc + g];
        }
        #pragma unroll
        for (int mi = 0; mi < 2; mi++)
            #pragma unroll
            for (int ni = 0; ni < 4; ni++)
                mma_tf32(d[mi][ni], a[mi], bf[ni]);
    }

    // --- epilogue: fp16 store with b1 fold on cols >= 64 (wn >= 2) ---
    #pragma unroll
    for (int mi = 0; mi < 2; mi++) {
        const int ra = row_base + r0 + mi * 16 + g;
        const int rb = ra + 8;
        #pragma unroll
        for (int ni = 0; ni < 4; ni++) {
            const int c = c0 + ni * 8 + 2 * t;
            float b0 = 0.f, b1v = 0.f;
            if (wn >= 2) { b0 = sb1[c - 64]; b1v = sb1[c - 63]; }
            if (ra < num_nodes) {
                __half2 h = __floats2half2_rn(d[mi][ni][0] + b0, d[mi][ni][1] + b1v);
                *reinterpret_cast<__half2*>(&g_PQh[(size_t)ra * 128 + c]) = h;
            }
            if (rb < num_nodes) {
                __half2 h = __floats2half2_rn(d[mi][ni][2] + b0, d[mi][ni][3] + b1v);
                *reinterpret_cast<__half2*>(&g_PQh[(size_t)rb * 128 + c]) = h;
            }
        }
    }
}

// log(v) for v in (0,1]: MUFU __logf except near 1 (log1p polynomial fixes
// MUFU absolute-error blowup where -log(v) ~ (1-v)).
__device__ __forceinline__ float fast_log01(float v)
{
    float t = v - 1.0f;
    float p = 1.0f + t * (-0.5f + t * (0.33333333f + t * (-0.25f + t * 0.2f)));
    p *= t;
    float m = __logf(v);
    return (v > 0.9375f) ? p : m;
}

// 8-lane partial dot: relu(p+q) . w in half2
__device__ __forceinline__ float dot8h(const uint4& pv, const uint4& qv, const uint4& wv)
{
    const __half2* p2 = reinterpret_cast<const __half2*>(&pv);
    const __half2* q2 = reinterpret_cast<const __half2*>(&qv);
    const __half2* w2 = reinterpret_cast<const __half2*>(&wv);
    const __half2 z2 = __float2half2_rn(0.f);
    __half2 acc2 = z2;
    #pragma unroll
    for (int i = 0; i < 4; i++) {
        __half2 h = __hmax2(__hadd2(p2[i], q2[i]), z2);
        acc2 = __hfma2(h, w2[i], acc2);
    }
    float2 f = __half22float2(acc2);
    return f.x + f.y;
}

// ---------------------------------------------------------------------------
// Kernel 2 (proven R16): per-edge MLP tail + fused gumbel-sigmoid, three-phase.
// Phase 0: threads 0..127 stage edge indices coalesced into smem.
// Phase 1: 8 lanes/edge, 4 edges/group; logits parked in smem.
// Phase 2: threads 0..127 run Gumbel tails densely (coalesced u1/u2/out).
//   out = L2 / (L2 + exp(-logit)*L1),  L = -log(u)
// ---------------------------------------------------------------------------
__global__ void __launch_bounds__(256) edge_kernel(
    const void* __restrict__ eidx_raw,
    const float* __restrict__ u1,
    const float* __restrict__ u2,
    const float* __restrict__ W2,
    const float* __restrict__ b2,
    float* __restrict__ out,
    int num_edges)
{
    __shared__ __half2 sW2h[HID / 2];
    __shared__ float sb2;
    __shared__ int2 sIdx[128];
    __shared__ float slog[128];

    const int tid  = threadIdx.x;
    const int base = blockIdx.x * 128;

    if (tid < HID / 2)
        sW2h[tid] = __floats2half2_rn(W2[2 * tid], W2[2 * tid + 1]);
    if (tid == HID / 2) sb2 = b2[0];

    if (tid < 128) {
        long long e = (long long)(base + tid);
        if (e >= num_edges) e = num_edges - 1;
        int row, col;
        if (g_idx_is64) {
            const long long* eidx = (const long long*)eidx_raw;
            row = (int)eidx[e];
            col = (int)eidx[(long long)num_edges + e];
        } else {
            const int* eidx = (const int*)eidx_raw;
            row = eidx[e];
            col = eidx[(long long)num_edges + e];
        }
        sIdx[tid] = make_int2(row, col);
    }
    __syncthreads();

    const int g  = tid >> 3;
    const int gl = tid & 7;

    const uint4 wv = *reinterpret_cast<const uint4*>(&sW2h[gl * 4]);

    int2 idx[4];
    #pragma unroll
    for (int j = 0; j < 4; j++) idx[j] = sIdx[j * 32 + g];

    uint4 pv[4], qv[4];
    #pragma unroll
    for (int j = 0; j < 4; j++) {
        pv[j] = *reinterpret_cast<const uint4*>(&g_PQh[(size_t)idx[j].x * 128 + gl * 8]);
        qv[j] = *reinterpret_cast<const uint4*>(&g_PQh[(size_t)idx[j].y * 128 + 64 + gl * 8]);
    }

    float p[4];
    #pragma unroll
    for (int j = 0; j < 4; j++) p[j] = dot8h(pv[j], qv[j], wv);

    #pragma unroll
    for (int j = 0; j < 4; j++) p[j] += __shfl_xor_sync(0xffffffffu, p[j], 1);
    #pragma unroll
    for (int j = 0; j < 4; j++) p[j] += __shfl_xor_sync(0xffffffffu, p[j], 2);
    #pragma unroll
    for (int j = 0; j < 4; j++) p[j] += __shfl_xor_sync(0xffffffffu, p[j], 4);

    if (gl == 0) {
        #pragma unroll
        for (int j = 0; j < 4; j++) slog[j * 32 + g] = p[j];
    }
    __syncthreads();

    if (tid < 128) {
        const long long e = (long long)base + tid;
        if (e < num_edges) {
            float logit = slog[tid] + sb2;
            float v1 = fminf(fmaxf(u1[e], EPS_F), 1.0f - EPS_F);
            float v2 = fminf(fmaxf(u2[e], EPS_F), 1.0f - EPS_F);
            float L1 = -fast_log01(v1);
            float L2 = -fast_log01(v2);
            float t  = __expf(-logit) * L1;
            out[e] = __fdividef(L2, L2 + t);
        }
    }
}

// ---------------------------------------------------------------------------
// Inputs (metadata order): node_embed, edge_index, u1, u2, W1, b1, W2, b2
// ---------------------------------------------------------------------------
extern "C" void kernel_launch(void* const* d_in, const int* in_sizes, int n_in,
                              void* d_out, int out_size)
{
    const float* node_embed = (const float*)d_in[0];
    const void*  edge_index = d_in[1];
    const float* u1         = (const float*)d_in[2];
    const float* u2         = (const float*)d_in[3];
    const float* W1         = (const float*)d_in[4];
    const float* b1         = (const float*)d_in[5];
    const float* W2         = (const float*)d_in[6];
    const float* b2         = (const float*)d_in[7];
    float*       out        = (float*)d_out;

    const int num_nodes = in_sizes[0] / EMBED;
    const int num_edges = in_sizes[2];

    static bool attr_set = false;
    if (!attr_set) {
        cudaFuncSetAttribute(pq_tc_kernel,
                             cudaFuncAttributeMaxDynamicSharedMemorySize, SMEM_BYTES);
        attr_set = true;
    }

    int gemm_blocks = (num_nodes + MTILE - 1) / MTILE;
    pq_tc_kernel<<<gemm_blocks, NTHREADS, SMEM_BYTES>>>(node_embed, W1, b1,
                                                        (const int*)edge_index,
                                                        num_nodes, num_edges);

    int edge_blocks = (num_edges + 127) / 128;
    edge_kernel<<<edge_blocks, 256>>>(edge_index, u1, u2, W2, b2, out, num_edges);
}